// round 13
// baseline (speedup 1.0000x reference)
#include <cuda_runtime.h>
#include <cuda_bf16.h>
#include <math.h>
#include <stdint.h>

#define BB 2
#define TT 2048
#define CC 2048
#define HH 16
#define DD 128
#define MM (BB*TT)   // 4096
#define ATT_SCALE 0.08838834764831845f

// ---------------- scratch (static device globals; no allocation) ----------------
__device__ float g_q[MM*CC];
__device__ float g_k[MM*CC];
__device__ float g_cos[TT*64];
__device__ float g_sin[TT*64];

// bf16 split planes
__device__ __nv_bfloat16 g_xh[MM*CC], g_xl[MM*CC];
__device__ __nv_bfloat16 g_yh[MM*CC], g_yl[MM*CC];
__device__ __nv_bfloat16 g_wqh[CC*CC], g_wql[CC*CC];
__device__ __nv_bfloat16 g_wkh[CC*CC], g_wkl[CC*CC];
__device__ __nv_bfloat16 g_wvh[CC*CC], g_wvl[CC*CC];
__device__ __nv_bfloat16 g_woh[CC*CC], g_wol[CC*CC];
// attention operand planes
__device__ __nv_bfloat16 g_qh[MM*CC], g_ql[MM*CC];   // RoPE'd, scaled
__device__ __nv_bfloat16 g_kh[MM*CC], g_kl[MM*CC];   // RoPE'd
__device__ __nv_bfloat16 g_vth[MM*CC], g_vtl[MM*CC]; // V transposed: [b,h][d][T]

// ================= helpers =================
__device__ __forceinline__ uint32_t smem_u32(const void* p) {
    uint32_t a;
    asm("{ .reg .u64 t; cvta.to.shared.u64 t, %1; cvt.u32.u64 %0, t; }" : "=r"(a) : "l"(p));
    return a;
}
#define SMEM_SWZ(o) ((o) ^ (((o) >> 3) & 0x70))

__device__ __forceinline__ void cp16(uint32_t dst, const void* src) {
    asm volatile("cp.async.cg.shared.global [%0], [%1], 16;" :: "r"(dst), "l"(src));
}
#define CP_COMMIT() asm volatile("cp.async.commit_group;" ::: "memory")
template<int N> __device__ __forceinline__ void cp_wait() {
    asm volatile("cp.async.wait_group %0;" :: "n"(N) : "memory");
}

__device__ __forceinline__ void ldm4(uint32_t& r0, uint32_t& r1, uint32_t& r2, uint32_t& r3,
                                     uint32_t addr) {
    asm volatile("ldmatrix.sync.aligned.m8n8.x4.shared.b16 {%0,%1,%2,%3}, [%4];"
                 : "=r"(r0), "=r"(r1), "=r"(r2), "=r"(r3) : "r"(addr));
}
__device__ __forceinline__ void mma16816(float& c0, float& c1, float& c2, float& c3,
                                         uint32_t a0, uint32_t a1, uint32_t a2, uint32_t a3,
                                         uint32_t b0, uint32_t b1) {
    asm volatile("mma.sync.aligned.m16n8k16.row.col.f32.bf16.bf16.f32 "
                 "{%0,%1,%2,%3}, {%4,%5,%6,%7}, {%8,%9}, {%0,%1,%2,%3};"
                 : "+f"(c0), "+f"(c1), "+f"(c2), "+f"(c3)
                 : "r"(a0), "r"(a1), "r"(a2), "r"(a3), "r"(b0), "r"(b1));
}

__device__ __forceinline__ void split2(float v, __nv_bfloat16& h, __nv_bfloat16& l) {
    h = __float2bfloat16(v);
    l = __float2bfloat16(v - __bfloat162float(h));
}
__device__ __forceinline__ uint32_t packbf2(float lo, float hi) {
    __nv_bfloat162 t = __floats2bfloat162_rn(lo, hi);
    return *(uint32_t*)&t;
}

// ---------------- RoPE tables ----------------
__global__ void __launch_bounds__(256) rope_table_kernel() {
    int idx = blockIdx.x * 256 + threadIdx.x;
    if (idx >= TT * 64) return;
    int t = idx >> 6, i = idx & 63;
    double invf = exp(-((double)(2 * i) / 128.0) * log(10000.0));
    double ang = (double)t * invf;
    double sn, cs;
    sincos(ang, &sn, &cs);
    g_cos[idx] = (float)cs;
    g_sin[idx] = (float)sn;
}

// ---------------- RoPE apply + bf16 split (Q scaled), 2x vectorized ----------------
__global__ void __launch_bounds__(256) rope_apply_split_kernel() {
    int idx = blockIdx.x * 256 + threadIdx.x;
    int p = idx & 31;
    int h = (idx >> 5) & (HH - 1);
    int t = (idx >> 9) & (TT - 1);
    int b = idx >> 20;
    int i2 = p * 2;
    size_t base = ((size_t)(b * TT + t)) * CC + h * DD;
    float2 c = *(const float2*)&g_cos[t * 64 + i2];
    float2 s = *(const float2*)&g_sin[t * 64 + i2];
    float2 qa = *(const float2*)&g_q[base + i2];
    float2 qb = *(const float2*)&g_q[base + 64 + i2];
    float2 ka = *(const float2*)&g_k[base + i2];
    float2 kb = *(const float2*)&g_k[base + 64 + i2];

    float qr0x = (qa.x * c.x - qb.x * s.x) * ATT_SCALE;
    float qr0y = (qa.y * c.y - qb.y * s.y) * ATT_SCALE;
    float qr1x = (qb.x * c.x + qa.x * s.x) * ATT_SCALE;
    float qr1y = (qb.y * c.y + qa.y * s.y) * ATT_SCALE;
    float kr0x = ka.x * c.x - kb.x * s.x;
    float kr0y = ka.y * c.y - kb.y * s.y;
    float kr1x = kb.x * c.x + ka.x * s.x;
    float kr1y = kb.y * c.y + ka.y * s.y;

    __nv_bfloat16 h0, l0, h1, l1;
    split2(qr0x, h0, l0); split2(qr0y, h1, l1);
    *(__nv_bfloat162*)&g_qh[base + i2] = __nv_bfloat162(h0, h1);
    *(__nv_bfloat162*)&g_ql[base + i2] = __nv_bfloat162(l0, l1);
    split2(qr1x, h0, l0); split2(qr1y, h1, l1);
    *(__nv_bfloat162*)&g_qh[base + 64 + i2] = __nv_bfloat162(h0, h1);
    *(__nv_bfloat162*)&g_ql[base + 64 + i2] = __nv_bfloat162(l0, l1);
    split2(kr0x, h0, l0); split2(kr0y, h1, l1);
    *(__nv_bfloat162*)&g_kh[base + i2] = __nv_bfloat162(h0, h1);
    *(__nv_bfloat162*)&g_kl[base + i2] = __nv_bfloat162(l0, l1);
    split2(kr1x, h0, l0); split2(kr1y, h1, l1);
    *(__nv_bfloat162*)&g_kh[base + 64 + i2] = __nv_bfloat162(h0, h1);
    *(__nv_bfloat162*)&g_kl[base + 64 + i2] = __nv_bfloat162(l0, l1);
}

// ---------------- plain split, 4x vectorized ----------------
__global__ void __launch_bounds__(256) conv_split_kernel(const float* __restrict__ src,
                                                         __nv_bfloat16* __restrict__ dh,
                                                         __nv_bfloat16* __restrict__ dl) {
    int i4 = (blockIdx.x * 256 + threadIdx.x) * 4;
    float4 v = *(const float4*)(src + i4);
    __nv_bfloat16 h0, l0, h1, l1, h2, l2, h3, l3;
    split2(v.x, h0, l0); split2(v.y, h1, l1);
    split2(v.z, h2, l2); split2(v.w, h3, l3);
    *(__nv_bfloat162*)&dh[i4]     = __nv_bfloat162(h0, h1);
    *(__nv_bfloat162*)&dh[i4 + 2] = __nv_bfloat162(h2, h3);
    *(__nv_bfloat162*)&dl[i4]     = __nv_bfloat162(l0, l1);
    *(__nv_bfloat162*)&dl[i4 + 2] = __nv_bfloat162(l2, l3);
}

// W[K,N] fp32 -> Wt_hi/lo[N,K] bf16 (transpose + split); z selects weight
__global__ void __launch_bounds__(256) conv_w4_kernel(const float* __restrict__ W0,
                                                      const float* __restrict__ W1,
                                                      const float* __restrict__ W2,
                                                      const float* __restrict__ W3) {
    __shared__ float tile[32][33];
    const int z = blockIdx.z;
    const float* W = (z == 0) ? W0 : (z == 1) ? W1 : (z == 2) ? W2 : W3;
    __nv_bfloat16* dh = (z == 0) ? g_wqh : (z == 1) ? g_wkh : (z == 2) ? g_wvh : g_woh;
    __nv_bfloat16* dl = (z == 0) ? g_wql : (z == 1) ? g_wkl : (z == 2) ? g_wvl : g_wol;
    int tx = threadIdx.x, ty = threadIdx.y;
    int n0 = blockIdx.x * 32, k0 = blockIdx.y * 32;
    #pragma unroll
    for (int j = 0; j < 32; j += 8)
        tile[ty + j][tx] = W[(size_t)(k0 + ty + j) * CC + n0 + tx];
    __syncthreads();
    #pragma unroll
    for (int j = 0; j < 32; j += 8) {
        float v = tile[tx][ty + j];
        __nv_bfloat16 h, l;
        split2(v, h, l);
        size_t o = (size_t)(n0 + ty + j) * CC + k0 + tx;
        dh[o] = h;
        dl[o] = l;
    }
}

// ---------------- HMMA bf16x3 GEMM, CTA tile 128M x 256N, 256 threads ----------------
// 4-deep K32-chunk pipeline: 2 super-buffers of 96KB, each 128B row holds two
// K32 chunks in its 64B halves. One barrier per chunk; loads issued after the
// barrier (in the compute shadow); cp_wait<2> keeps 2 chunks in flight.
#define A_PLANE 16384               // 128 rows x 128B (2 K32 chunks)
#define B_PLANE 32768               // 256 rows x 128B
#define STAGE_BYTES (2 * A_PLANE + 2 * B_PLANE)     // 98304 per super-buffer
#define GEMM_SMEM (2 * STAGE_BYTES)                 // 196608
#define OFF_AH 0
#define OFF_AL A_PLANE
#define OFF_BH (2*A_PLANE)
#define OFF_BL (2*A_PLANE + B_PLANE)
#define VT_STRIDE 136               // bf16 elems per col in V bounce buffer
#define NCHUNK 64                   // K=2048 / 32

extern __shared__ __align__(1024) char smg[];

__global__ void __launch_bounds__(256, 1)
gemm_bf16x3(const __nv_bfloat16* __restrict__ Ah, const __nv_bfloat16* __restrict__ Al,
            const __nv_bfloat16* __restrict__ Bh0, const __nv_bfloat16* __restrict__ Bl0,
            const __nv_bfloat16* __restrict__ Bh1, const __nv_bfloat16* __restrict__ Bl1,
            const __nv_bfloat16* __restrict__ Bh2, const __nv_bfloat16* __restrict__ Bl2,
            float* C0, float* C1) {
    const int tid = threadIdx.x;
    const int wid = tid >> 5;
    const int lane = tid & 31;
    const uint32_t sb = smem_u32(smg);
    const int nb = blockIdx.x * 256;
    const int mb = blockIdx.y * 128;
    const int z = blockIdx.z;
    const __nv_bfloat16* Bh = (z == 0) ? Bh0 : (z == 1) ? Bh1 : Bh2;
    const __nv_bfloat16* Bl = (z == 0) ? Bl0 : (z == 1) ? Bl1 : Bl2;

    const int wm = wid & 1;
    const int wn = wid >> 1;
    const int sub = lane >> 3;
    const int l7 = lane & 7;
    const uint32_t xorv = (uint32_t)l7 << 4;
    const int half_a = sub & 1;
    const int khalf = (sub >> 1) * 16;

    uint32_t a_row[4], b_row[4];
    #pragma unroll
    for (int mt = 0; mt < 4; ++mt)
        a_row[mt] = (uint32_t)(wm * 64 + mt * 16 + half_a * 8 + l7) * 128;
    #pragma unroll
    for (int nt = 0; nt < 4; ++nt)
        b_row[nt] = (uint32_t)(wn * 64 + nt * 16 + half_a * 8 + l7) * 128;

    float acc[4][8][4];
    #pragma unroll
    for (int i = 0; i < 4; ++i)
        #pragma unroll
        for (int j = 0; j < 8; ++j)
            #pragma unroll
            for (int r = 0; r < 4; ++r) acc[i][j][r] = 0.f;

    // load one K32 chunk: super = (it>>1)&1, half = it&1
    auto load_chunk = [&](int it) {
        const uint32_t bbase = sb + (uint32_t)((it >> 1) & 1) * STAGE_BYTES;
        const uint32_t hoff = (uint32_t)(it & 1) * 64;
        const size_t k0 = (size_t)it * 32;
        #pragma unroll
        for (int c = tid; c < 512; c += 256) {      // A: 128 rows x 4 x16B
            const int row = c >> 2, ch = c & 3;
            const uint32_t soff = SMEM_SWZ((uint32_t)(row * 128 + hoff + ch * 16));
            const size_t aoff = (size_t)(mb + row) * CC + k0 + ch * 8;
            cp16(bbase + OFF_AH + soff, Ah + aoff);
            cp16(bbase + OFF_AL + soff, Al + aoff);
        }
        #pragma unroll
        for (int c = tid; c < 1024; c += 256) {     // B: 256 rows x 4 x16B
            const int row = c >> 2, ch = c & 3;
            const uint32_t soff = SMEM_SWZ((uint32_t)(row * 128 + hoff + ch * 16));
            const size_t boff = (size_t)(nb + row) * CC + k0 + ch * 8;
            cp16(bbase + OFF_BH + soff, Bh + boff);
            cp16(bbase + OFF_BL + soff, Bl + boff);
        }
        CP_COMMIT();
    };

    load_chunk(0);
    load_chunk(1);
    load_chunk(2);

    for (int it = 0; it < NCHUNK; ++it) {
        if (it <= NCHUNK - 3) cp_wait<2>();
        else if (it == NCHUNK - 2) cp_wait<1>();
        else cp_wait<0>();
        __syncthreads();                     // chunk(it) visible; all done with compute(it-1)
        if (it + 3 < NCHUNK) load_chunk(it + 3);   // issued in compute shadow; writes disjoint half

        const uint32_t base = sb + (uint32_t)((it >> 1) & 1) * STAGE_BYTES;
        const uint32_t hoff = (uint32_t)(it & 1) * 64;
        #pragma unroll
        for (int ks = 0; ks < 2; ++ks) {
            const uint32_t col = (uint32_t)(hoff + ks * 32 + khalf) ^ xorv;

            uint32_t ah[4][4], al[4][4];
            #pragma unroll
            for (int mt = 0; mt < 4; ++mt) {
                ldm4(ah[mt][0], ah[mt][1], ah[mt][2], ah[mt][3],
                     base + OFF_AH + a_row[mt] + col);
                ldm4(al[mt][0], al[mt][1], al[mt][2], al[mt][3],
                     base + OFF_AL + a_row[mt] + col);
            }
            #pragma unroll
            for (int nt = 0; nt < 4; ++nt) {
                uint32_t bh0, bh1, bh2, bh3, bl0, bl1, bl2, bl3;
                ldm4(bh0, bh1, bh2, bh3, base + OFF_BH + b_row[nt] + col);
                ldm4(bl0, bl1, bl2, bl3, base + OFF_BL + b_row[nt] + col);
                #pragma unroll
                for (int mt = 0; mt < 4; ++mt) {
                    float* c0 = acc[mt][nt * 2];
                    float* c1 = acc[mt][nt * 2 + 1];
                    mma16816(c0[0], c0[1], c0[2], c0[3],
                             ah[mt][0], ah[mt][1], ah[mt][2], ah[mt][3], bh0, bh2);
                    mma16816(c1[0], c1[1], c1[2], c1[3],
                             ah[mt][0], ah[mt][1], ah[mt][2], ah[mt][3], bh1, bh3);
                    mma16816(c0[0], c0[1], c0[2], c0[3],
                             ah[mt][0], ah[mt][1], ah[mt][2], ah[mt][3], bl0, bl2);
                    mma16816(c1[0], c1[1], c1[2], c1[3],
                             ah[mt][0], ah[mt][1], ah[mt][2], ah[mt][3], bl1, bl3);
                    mma16816(c0[0], c0[1], c0[2], c0[3],
                             al[mt][0], al[mt][1], al[mt][2], al[mt][3], bh0, bh2);
                    mma16816(c1[0], c1[1], c1[2], c1[3],
                             al[mt][0], al[mt][1], al[mt][2], al[mt][3], bh1, bh3);
                }
            }
        }
    }

    const int qrow = lane >> 2;
    const int qcol = (lane & 3) * 2;

    if (z != 2) {
        float* C = (z == 0) ? C0 : C1;
        #pragma unroll
        for (int mt = 0; mt < 4; ++mt) {
            const int row0 = mb + wm * 64 + mt * 16 + qrow;
            #pragma unroll
            for (int nt = 0; nt < 8; ++nt) {
                const int col = nb + wn * 64 + nt * 8 + qcol;
                float2 v0 = {acc[mt][nt][0], acc[mt][nt][1]};
                float2 v1 = {acc[mt][nt][2], acc[mt][nt][3]};
                *(float2*)(C + (size_t)row0 * CC + col)       = v0;
                *(float2*)(C + (size_t)(row0 + 8) * CC + col) = v1;
            }
        }
    } else {
        // V path: split to bf16 hi/lo, transpose via smem bounce, write [b,h][d][T]
        __syncthreads();    // all warps done with smem tiles before reuse as bounce
        __nv_bfloat16* shh = (__nv_bfloat16*)smg;               // [256][VT_STRIDE]
        __nv_bfloat16* shl = shh + 256 * VT_STRIDE;
        #pragma unroll
        for (int mt = 0; mt < 4; ++mt) {
            const int r0 = wm * 64 + mt * 16 + qrow;
            #pragma unroll
            for (int nt = 0; nt < 8; ++nt) {
                const int cl = wn * 64 + nt * 8 + qcol;
                __nv_bfloat16 h, l;
                split2(acc[mt][nt][0], h, l);
                shh[cl * VT_STRIDE + r0] = h;       shl[cl * VT_STRIDE + r0] = l;
                split2(acc[mt][nt][1], h, l);
                shh[(cl + 1) * VT_STRIDE + r0] = h; shl[(cl + 1) * VT_STRIDE + r0] = l;
                split2(acc[mt][nt][2], h, l);
                shh[cl * VT_STRIDE + r0 + 8] = h;       shl[cl * VT_STRIDE + r0 + 8] = l;
                split2(acc[mt][nt][3], h, l);
                shh[(cl + 1) * VT_STRIDE + r0 + 8] = h; shl[(cl + 1) * VT_STRIDE + r0 + 8] = l;
            }
        }
        __syncthreads();
        const int b = mb >> 11;
        const int tloc = mb & (TT - 1);
        const int r = lane * 4;
        for (int ci = wid; ci < 256; ci += 8) {
            const int gcol = nb + ci;               // h*128 + d
            const int hh = gcol >> 7, d = gcol & 127;
            const size_t drow = ((size_t)(b * HH + hh) * DD + d) * TT + tloc;
            uint2 wh = *(uint2*)&shh[ci * VT_STRIDE + r];
            uint2 wl = *(uint2*)&shl[ci * VT_STRIDE + r];
            *(uint2*)(g_vth + drow + r) = wh;
            *(uint2*)(g_vtl + drow + r) = wl;
        }
    }
}

// ---------------- HMMA bf16x3 causal flash attention ----------------
#define SM_QH 0
#define SM_QL 32768
#define SM_STG 65536
#define SM_STG_BYTES 65536
#define ATT_SMEM2 (SM_STG + 2 * SM_STG_BYTES)   // 196608

extern __shared__ __align__(1024) char sma[];

__global__ void __launch_bounds__(256, 1) attn_hmma() {
    const int qb = (int)(gridDim.x - 1 - blockIdx.x);   // long CTAs launch first
    const int h  = blockIdx.y;
    const int b  = blockIdx.z;
    const int tid = threadIdx.x;
    const int wid = tid >> 5;
    const int lane = tid & 31;
    const uint32_t sb = smem_u32(sma);

    const int l7 = lane & 7;
    const int sub = lane >> 3;
    const int half_a = sub & 1;
    const int khalf = (sub >> 1) * 16;
    const uint32_t xorv = (uint32_t)l7 << 4;

    const size_t qrowbase = ((size_t)(b * TT + qb * 128)) * CC + h * DD;

    #pragma unroll
    for (int c = tid; c < 2048; c += 256) {
        const int row = c >> 4;
        const int ch = c & 15;
        const int dch = ch >> 3, chi = ch & 7;
        const uint32_t soff = (uint32_t)dch * 16384 + SMEM_SWZ((uint32_t)(row * 128 + chi * 16));
        const size_t goff = qrowbase + (size_t)row * CC + dch * 64 + chi * 8;
        cp16(sb + SM_QH + soff, g_qh + goff);
        cp16(sb + SM_QL + soff, g_ql + goff);
    }
    CP_COMMIT();

    const int kb_last = 2 * qb + 1;

    auto load_stage = [&](int kb) {
        const uint32_t base = sb + SM_STG + (kb & 1) * SM_STG_BYTES;
        const size_t krow0 = ((size_t)(b * TT + kb * 64)) * CC + h * DD;
        #pragma unroll
        for (int c = tid; c < 1024; c += 256) {
            const int row = c >> 4;
            const int ch = c & 15;
            const int dch = ch >> 3, chi = ch & 7;
            const uint32_t soff = (uint32_t)dch * 8192 + SMEM_SWZ((uint32_t)(row * 128 + chi * 16));
            const size_t goff = krow0 + (size_t)row * CC + dch * 64 + chi * 8;
            cp16(base + 0 + soff, g_kh + goff);
            cp16(base + 16384 + soff, g_kl + goff);
        }
        const size_t vbase = ((size_t)((b * HH + h) * DD)) * TT + (size_t)kb * 64;
        #pragma unroll
        for (int c = tid; c < 1024; c += 256) {
            const int row = c >> 3;
            const int chi = c & 7;
            const uint32_t soff = SMEM_SWZ((uint32_t)(row * 128 + chi * 16));
            const size_t goff = vbase + (size_t)row * TT + chi * 8;
            cp16(base + 32768 + soff, g_vth + goff);
            cp16(base + 49152 + soff, g_vtl + goff);
        }
        CP_COMMIT();
    };

    load_stage(0);
    cp_wait<1>();          // Q arrived; stage 0 may still be loading
    __syncthreads();

    uint32_t qhf[8][4], qlf[8][4];
    {
        const uint32_t arow = (uint32_t)(wid * 16 + half_a * 8 + l7) * 128;
        #pragma unroll
        for (int kd = 0; kd < 8; ++kd) {
            const uint32_t col = (uint32_t)((kd & 3) * 32 + khalf) ^ xorv;
            const uint32_t off = (uint32_t)(kd >> 2) * 16384 + arow + col;
            ldm4(qhf[kd][0], qhf[kd][1], qhf[kd][2], qhf[kd][3], sb + SM_QH + off);
            ldm4(qlf[kd][0], qlf[kd][1], qlf[kd][2], qlf[kd][3], sb + SM_QL + off);
        }
    }

    float of[16][4];
    #pragma unroll
    for (int i = 0; i < 16; ++i)
        #pragma unroll
        for (int j = 0; j < 4; ++j) of[i][j] = 0.f;
    float mro0 = -1e30f, mro1 = -1e30f, lro0 = 0.f, lro1 = 0.f;

    const int row0g = qb * 128 + wid * 16 + (lane >> 2);
    const int colg0 = 2 * (lane & 3);

    for (int kb = 0; kb <= kb_last; ++kb) {
        if (kb + 1 <= kb_last) {
            load_stage(kb + 1);   // prefetch in flight BEFORE waiting
            cp_wait<1>();
        } else {
            cp_wait<0>();
        }
        __syncthreads();

        const uint32_t base = sb + SM_STG + (kb & 1) * SM_STG_BYTES;

        float sacc[8][4];
        #pragma unroll
        for (int nt = 0; nt < 8; ++nt)
            #pragma unroll
            for (int j = 0; j < 4; ++j) sacc[nt][j] = 0.f;

        #pragma unroll
        for (int kd = 0; kd < 8; ++kd) {
            const uint32_t col = (uint32_t)((kd & 3) * 32 + khalf) ^ xorv;
            const uint32_t chb = (uint32_t)(kd >> 2) * 8192;
            #pragma unroll
            for (int ntp = 0; ntp < 4; ++ntp) {
                const uint32_t rowb = (uint32_t)(ntp * 16 + half_a * 8 + l7) * 128;
                uint32_t kh0, kh1, kh2, kh3, kl0, kl1, kl2, kl3;
                ldm4(kh0, kh1, kh2, kh3, base + chb + rowb + col);
                ldm4(kl0, kl1, kl2, kl3, base + 16384 + chb + rowb + col);
                float* c0 = sacc[ntp * 2];
                float* c1 = sacc[ntp * 2 + 1];
                mma16816(c0[0], c0[1], c0[2], c0[3],
                         qhf[kd][0], qhf[kd][1], qhf[kd][2], qhf[kd][3], kh0, kh2);
                mma16816(c1[0], c1[1], c1[2], c1[3],
                         qhf[kd][0], qhf[kd][1], qhf[kd][2], qhf[kd][3], kh1, kh3);
                mma16816(c0[0], c0[1], c0[2], c0[3],
                         qhf[kd][0], qhf[kd][1], qhf[kd][2], qhf[kd][3], kl0, kl2);
                mma16816(c1[0], c1[1], c1[2], c1[3],
                         qhf[kd][0], qhf[kd][1], qhf[kd][2], qhf[kd][3], kl1, kl3);
                mma16816(c0[0], c0[1], c0[2], c0[3],
                         qlf[kd][0], qlf[kd][1], qlf[kd][2], qlf[kd][3], kh0, kh2);
                mma16816(c1[0], c1[1], c1[2], c1[3],
                         qlf[kd][0], qlf[kd][1], qlf[kd][2], qlf[kd][3], kh1, kh3);
            }
        }

        if (kb * 64 + 63 > qb * 128 + wid * 16) {
            const int cb = kb * 64 + colg0;
            #pragma unroll
            for (int nt = 0; nt < 8; ++nt) {
                const int c0 = cb + nt * 8, c1 = c0 + 1;
                if (c0 > row0g) sacc[nt][0] = -1e30f;
                if (c1 > row0g) sacc[nt][1] = -1e30f;
                if (c0 > row0g + 8) sacc[nt][2] = -1e30f;
                if (c1 > row0g + 8) sacc[nt][3] = -1e30f;
            }
        }

        float mx0 = -1e30f, mx1 = -1e30f;
        #pragma unroll
        for (int nt = 0; nt < 8; ++nt) {
            mx0 = fmaxf(mx0, fmaxf(sacc[nt][0], sacc[nt][1]));
            mx1 = fmaxf(mx1, fmaxf(sacc[nt][2], sacc[nt][3]));
        }
        mx0 = fmaxf(mx0, __shfl_xor_sync(0xffffffffu, mx0, 1));
        mx0 = fmaxf(mx0, __shfl_xor_sync(0xffffffffu, mx0, 2));
        mx1 = fmaxf(mx1, __shfl_xor_sync(0xffffffffu, mx1, 1));
        mx1 = fmaxf(mx1, __shfl_xor_sync(0xffffffffu, mx1, 2));

        const float mn0 = fmaxf(mro0, mx0);
        const float mn1 = fmaxf(mro1, mx1);
        const float al0 = __expf(mro0 - mn0);
        const float al1 = __expf(mro1 - mn1);
        mro0 = mn0; mro1 = mn1;

        float rs0 = 0.f, rs1 = 0.f;
        #pragma unroll
        for (int nt = 0; nt < 8; ++nt) {
            float p0 = __expf(sacc[nt][0] - mn0);
            float p1 = __expf(sacc[nt][1] - mn0);
            float p2 = __expf(sacc[nt][2] - mn1);
            float p3 = __expf(sacc[nt][3] - mn1);
            sacc[nt][0] = p0; sacc[nt][1] = p1; sacc[nt][2] = p2; sacc[nt][3] = p3;
            rs0 += p0 + p1;
            rs1 += p2 + p3;
        }
        rs0 += __shfl_xor_sync(0xffffffffu, rs0, 1);
        rs0 += __shfl_xor_sync(0xffffffffu, rs0, 2);
        rs1 += __shfl_xor_sync(0xffffffffu, rs1, 1);
        rs1 += __shfl_xor_sync(0xffffffffu, rs1, 2);
        lro0 = lro0 * al0 + rs0;
        lro1 = lro1 * al1 + rs1;

        #pragma unroll
        for (int dt = 0; dt < 16; ++dt) {
            of[dt][0] *= al0; of[dt][1] *= al0;
            of[dt][2] *= al1; of[dt][3] *= al1;
        }

        uint32_t pah[4][4], pal[4][4];
        #pragma unroll
        for (int g = 0; g < 4; ++g) {
            const float* pe = sacc[2 * g];
            const float* po = sacc[2 * g + 1];
            pah[g][0] = packbf2(pe[0], pe[1]);
            pah[g][1] = packbf2(pe[2], pe[3]);
            pah[g][2] = packbf2(po[0], po[1]);
            pah[g][3] = packbf2(po[2], po[3]);
            __nv_bfloat162* bh;
            bh = (__nv_bfloat162*)&pah[g][0];
            pal[g][0] = packbf2(pe[0] - __bfloat162float(bh->x), pe[1] - __bfloat162float(bh->y));
            bh = (__nv_bfloat162*)&pah[g][1];
            pal[g][1] = packbf2(pe[2] - __bfloat162float(bh->x), pe[3] - __bfloat162float(bh->y));
            bh = (__nv_bfloat162*)&pah[g][2];
            pal[g][2] = packbf2(po[0] - __bfloat162float(bh->x), po[1] - __bfloat162float(bh->y));
            bh = (__nv_bfloat162*)&pah[g][3];
            pal[g][3] = packbf2(po[2] - __bfloat162float(bh->x), po[3] - __bfloat162float(bh->y));
        }

        #pragma unroll
        for (int g = 0; g < 4; ++g) {
            const uint32_t col = (uint32_t)(g * 32 + khalf) ^ xorv;
            #pragma unroll
            for (int dt = 0; dt < 8; ++dt) {
                const uint32_t rowb = (uint32_t)(dt * 16 + half_a * 8 + l7) * 128;
                uint32_t vh0, vh1, vh2, vh3, vl0, vl1, vl2, vl3;
                ldm4(vh0, vh1, vh2, vh3, base + 32768 + rowb + col);
                ldm4(vl0, vl1, vl2, vl3, base + 49152 + rowb + col);
                float* o0 = of[dt * 2];
                float* o1 = of[dt * 2 + 1];
                mma16816(o0[0], o0[1], o0[2], o0[3],
                         pah[g][0], pah[g][1], pah[g][2], pah[g][3], vh0, vh2);
                mma16816(o1[0], o1[1], o1[2], o1[3],
                         pah[g][0], pah[g][1], pah[g][2], pah[g][3], vh1, vh3);
                mma16816(o0[0], o0[1], o0[2], o0[3],
                         pah[g][0], pah[g][1], pah[g][2], pah[g][3], vl0, vl2);
                mma16816(o1[0], o1[1], o1[2], o1[3],
                         pah[g][0], pah[g][1], pah[g][2], pah[g][3], vl1, vl3);
                mma16816(o0[0], o0[1], o0[2], o0[3],
                         pal[g][0], pal[g][1], pal[g][2], pal[g][3], vh0, vh2);
                mma16816(o1[0], o1[1], o1[2], o1[3],
                         pal[g][0], pal[g][1], pal[g][2], pal[g][3], vh1, vh3);
            }
        }
        __syncthreads();
    }

    // ---- epilogue: write bf16 hi/lo planes for the O-projection directly ----
    const float inv0 = 1.f / lro0;
    const float inv1 = 1.f / lro1;
    const size_t obase = qrowbase + (size_t)(wid * 16 + (lane >> 2)) * CC + colg0;
    #pragma unroll
    for (int dt = 0; dt < 16; ++dt) {
        float v00 = of[dt][0] * inv0, v01 = of[dt][1] * inv0;
        float v10 = of[dt][2] * inv1, v11 = of[dt][3] * inv1;
        __nv_bfloat16 h0, l0, h1, l1;
        split2(v00, h0, l0); split2(v01, h1, l1);
        *(__nv_bfloat162*)(g_yh + obase + dt * 8) = __nv_bfloat162(h0, h1);
        *(__nv_bfloat162*)(g_yl + obase + dt * 8) = __nv_bfloat162(l0, l1);
        split2(v10, h0, l0); split2(v11, h1, l1);
        *(__nv_bfloat162*)(g_yh + obase + 8 * CC + dt * 8) = __nv_bfloat162(h0, h1);
        *(__nv_bfloat162*)(g_yl + obase + 8 * CC + dt * 8) = __nv_bfloat162(l0, l1);
    }
}

// ---------------- launch ----------------
extern "C" void kernel_launch(void* const* d_in, const int* in_sizes, int n_in,
                              void* d_out, int out_size) {
    const float* x  = (const float*)d_in[0];
    const float* wq = (const float*)d_in[1];
    const float* wk = (const float*)d_in[2];
    const float* wv = (const float*)d_in[3];
    const float* wo = (const float*)d_in[4];
    float* out = (float*)d_out;

    float *q, *k;
    cudaGetSymbolAddress((void**)&q, g_q);
    cudaGetSymbolAddress((void**)&k, g_k);

    __nv_bfloat16 *xh, *xl, *yh, *yl;
    __nv_bfloat16 *wqh, *wql, *wkh, *wkl, *wvh, *wvl, *woh, *wol;
    cudaGetSymbolAddress((void**)&xh, g_xh);   cudaGetSymbolAddress((void**)&xl, g_xl);
    cudaGetSymbolAddress((void**)&yh, g_yh);   cudaGetSymbolAddress((void**)&yl, g_yl);
    cudaGetSymbolAddress((void**)&wqh, g_wqh); cudaGetSymbolAddress((void**)&wql, g_wql);
    cudaGetSymbolAddress((void**)&wkh, g_wkh); cudaGetSymbolAddress((void**)&wkl, g_wkl);
    cudaGetSymbolAddress((void**)&wvh, g_wvh); cudaGetSymbolAddress((void**)&wvl, g_wvl);
    cudaGetSymbolAddress((void**)&woh, g_woh); cudaGetSymbolAddress((void**)&wol, g_wol);

    rope_table_kernel<<<512, 256>>>();
    conv_split_kernel<<<(MM * CC) / 1024, 256>>>(x, xh, xl);
    conv_w4_kernel<<<dim3(CC / 32, CC / 32, 4), dim3(32, 8)>>>(wq, wk, wv, wo);

    cudaFuncSetAttribute(gemm_bf16x3, cudaFuncAttributeMaxDynamicSharedMemorySize, GEMM_SMEM);

    // fused QKV projection; z==2 (V) writes transposed bf16 planes directly
    gemm_bf16x3<<<dim3(CC / 256, MM / 128, 3), 256, GEMM_SMEM>>>(
        xh, xl, wqh, wql, wkh, wkl, wvh, wvl, q, k);

    rope_apply_split_kernel<<<(BB * TT * HH * 32) / 256, 256>>>();

    cudaFuncSetAttribute(attn_hmma, cudaFuncAttributeMaxDynamicSharedMemorySize, ATT_SMEM2);
    attn_hmma<<<dim3(TT / 128, HH, BB), 256, ATT_SMEM2>>>();

    // output projection (z==0 path, C0 = out)
    gemm_bf16x3<<<dim3(CC / 256, MM / 128, 1), 256, GEMM_SMEM>>>(
        yh, yl, woh, wol, woh, wol, woh, wol, out, out);
}

// round 14
// speedup vs baseline: 1.0813x; 1.0813x over previous
#include <cuda_runtime.h>
#include <cuda_bf16.h>
#include <math.h>
#include <stdint.h>

#define BB 2
#define TT 2048
#define CC 2048
#define HH 16
#define DD 128
#define MM (BB*TT)   // 4096
#define ATT_SCALE 0.08838834764831845f

// ---------------- scratch (static device globals; no allocation) ----------------
__device__ float g_q[MM*CC];
__device__ float g_k[MM*CC];
__device__ float g_cos[TT*64];
__device__ float g_sin[TT*64];

// bf16 split planes
__device__ __nv_bfloat16 g_xh[MM*CC], g_xl[MM*CC];
__device__ __nv_bfloat16 g_yh[MM*CC], g_yl[MM*CC];
__device__ __nv_bfloat16 g_wqh[CC*CC], g_wql[CC*CC];
__device__ __nv_bfloat16 g_wkh[CC*CC], g_wkl[CC*CC];
__device__ __nv_bfloat16 g_wvh[CC*CC], g_wvl[CC*CC];
__device__ __nv_bfloat16 g_woh[CC*CC], g_wol[CC*CC];
// attention operand planes
__device__ __nv_bfloat16 g_qh[MM*CC], g_ql[MM*CC];   // RoPE'd, scaled
__device__ __nv_bfloat16 g_kh[MM*CC], g_kl[MM*CC];   // RoPE'd
__device__ __nv_bfloat16 g_vth[MM*CC], g_vtl[MM*CC]; // V transposed: [b,h][d][T]

// ================= helpers =================
__device__ __forceinline__ uint32_t smem_u32(const void* p) {
    uint32_t a;
    asm("{ .reg .u64 t; cvta.to.shared.u64 t, %1; cvt.u32.u64 %0, t; }" : "=r"(a) : "l"(p));
    return a;
}
#define SMEM_SWZ(o) ((o) ^ (((o) >> 3) & 0x70))

__device__ __forceinline__ void cp16(uint32_t dst, const void* src) {
    asm volatile("cp.async.cg.shared.global [%0], [%1], 16;" :: "r"(dst), "l"(src));
}
#define CP_COMMIT() asm volatile("cp.async.commit_group;" ::: "memory")
template<int N> __device__ __forceinline__ void cp_wait() {
    asm volatile("cp.async.wait_group %0;" :: "n"(N) : "memory");
}

__device__ __forceinline__ void ldm4(uint32_t& r0, uint32_t& r1, uint32_t& r2, uint32_t& r3,
                                     uint32_t addr) {
    asm volatile("ldmatrix.sync.aligned.m8n8.x4.shared.b16 {%0,%1,%2,%3}, [%4];"
                 : "=r"(r0), "=r"(r1), "=r"(r2), "=r"(r3) : "r"(addr));
}
__device__ __forceinline__ void mma16816(float& c0, float& c1, float& c2, float& c3,
                                         uint32_t a0, uint32_t a1, uint32_t a2, uint32_t a3,
                                         uint32_t b0, uint32_t b1) {
    asm volatile("mma.sync.aligned.m16n8k16.row.col.f32.bf16.bf16.f32 "
                 "{%0,%1,%2,%3}, {%4,%5,%6,%7}, {%8,%9}, {%0,%1,%2,%3};"
                 : "+f"(c0), "+f"(c1), "+f"(c2), "+f"(c3)
                 : "r"(a0), "r"(a1), "r"(a2), "r"(a3), "r"(b0), "r"(b1));
}

__device__ __forceinline__ void split2(float v, __nv_bfloat16& h, __nv_bfloat16& l) {
    h = __float2bfloat16(v);
    l = __float2bfloat16(v - __bfloat162float(h));
}
__device__ __forceinline__ uint32_t packbf2(float lo, float hi) {
    __nv_bfloat162 t = __floats2bfloat162_rn(lo, hi);
    return *(uint32_t*)&t;
}

// ---------------- RoPE tables ----------------
__global__ void __launch_bounds__(256) rope_table_kernel() {
    int idx = blockIdx.x * 256 + threadIdx.x;
    if (idx >= TT * 64) return;
    int t = idx >> 6, i = idx & 63;
    double invf = exp(-((double)(2 * i) / 128.0) * log(10000.0));
    double ang = (double)t * invf;
    double sn, cs;
    sincos(ang, &sn, &cs);
    g_cos[idx] = (float)cs;
    g_sin[idx] = (float)sn;
}

// ---------------- RoPE apply + bf16 split (Q scaled), 2x vectorized ----------------
__global__ void __launch_bounds__(256) rope_apply_split_kernel() {
    int idx = blockIdx.x * 256 + threadIdx.x;
    int p = idx & 31;
    int h = (idx >> 5) & (HH - 1);
    int t = (idx >> 9) & (TT - 1);
    int b = idx >> 20;
    int i2 = p * 2;
    size_t base = ((size_t)(b * TT + t)) * CC + h * DD;
    float2 c = *(const float2*)&g_cos[t * 64 + i2];
    float2 s = *(const float2*)&g_sin[t * 64 + i2];
    float2 qa = *(const float2*)&g_q[base + i2];
    float2 qb = *(const float2*)&g_q[base + 64 + i2];
    float2 ka = *(const float2*)&g_k[base + i2];
    float2 kb = *(const float2*)&g_k[base + 64 + i2];

    float qr0x = (qa.x * c.x - qb.x * s.x) * ATT_SCALE;
    float qr0y = (qa.y * c.y - qb.y * s.y) * ATT_SCALE;
    float qr1x = (qb.x * c.x + qa.x * s.x) * ATT_SCALE;
    float qr1y = (qb.y * c.y + qa.y * s.y) * ATT_SCALE;
    float kr0x = ka.x * c.x - kb.x * s.x;
    float kr0y = ka.y * c.y - kb.y * s.y;
    float kr1x = kb.x * c.x + ka.x * s.x;
    float kr1y = kb.y * c.y + ka.y * s.y;

    __nv_bfloat16 h0, l0, h1, l1;
    split2(qr0x, h0, l0); split2(qr0y, h1, l1);
    *(__nv_bfloat162*)&g_qh[base + i2] = __nv_bfloat162(h0, h1);
    *(__nv_bfloat162*)&g_ql[base + i2] = __nv_bfloat162(l0, l1);
    split2(qr1x, h0, l0); split2(qr1y, h1, l1);
    *(__nv_bfloat162*)&g_qh[base + 64 + i2] = __nv_bfloat162(h0, h1);
    *(__nv_bfloat162*)&g_ql[base + 64 + i2] = __nv_bfloat162(l0, l1);
    split2(kr0x, h0, l0); split2(kr0y, h1, l1);
    *(__nv_bfloat162*)&g_kh[base + i2] = __nv_bfloat162(h0, h1);
    *(__nv_bfloat162*)&g_kl[base + i2] = __nv_bfloat162(l0, l1);
    split2(kr1x, h0, l0); split2(kr1y, h1, l1);
    *(__nv_bfloat162*)&g_kh[base + 64 + i2] = __nv_bfloat162(h0, h1);
    *(__nv_bfloat162*)&g_kl[base + 64 + i2] = __nv_bfloat162(l0, l1);
}

// ---------------- plain split, 4x vectorized ----------------
__global__ void __launch_bounds__(256) conv_split_kernel(const float* __restrict__ src,
                                                         __nv_bfloat16* __restrict__ dh,
                                                         __nv_bfloat16* __restrict__ dl) {
    int i4 = (blockIdx.x * 256 + threadIdx.x) * 4;
    float4 v = *(const float4*)(src + i4);
    __nv_bfloat16 h0, l0, h1, l1, h2, l2, h3, l3;
    split2(v.x, h0, l0); split2(v.y, h1, l1);
    split2(v.z, h2, l2); split2(v.w, h3, l3);
    *(__nv_bfloat162*)&dh[i4]     = __nv_bfloat162(h0, h1);
    *(__nv_bfloat162*)&dh[i4 + 2] = __nv_bfloat162(h2, h3);
    *(__nv_bfloat162*)&dl[i4]     = __nv_bfloat162(l0, l1);
    *(__nv_bfloat162*)&dl[i4 + 2] = __nv_bfloat162(l2, l3);
}

// W[K,N] fp32 -> Wt_hi/lo[N,K] bf16 (transpose + split); z selects weight
__global__ void __launch_bounds__(256) conv_w4_kernel(const float* __restrict__ W0,
                                                      const float* __restrict__ W1,
                                                      const float* __restrict__ W2,
                                                      const float* __restrict__ W3) {
    __shared__ float tile[32][33];
    const int z = blockIdx.z;
    const float* W = (z == 0) ? W0 : (z == 1) ? W1 : (z == 2) ? W2 : W3;
    __nv_bfloat16* dh = (z == 0) ? g_wqh : (z == 1) ? g_wkh : (z == 2) ? g_wvh : g_woh;
    __nv_bfloat16* dl = (z == 0) ? g_wql : (z == 1) ? g_wkl : (z == 2) ? g_wvl : g_wol;
    int tx = threadIdx.x, ty = threadIdx.y;
    int n0 = blockIdx.x * 32, k0 = blockIdx.y * 32;
    #pragma unroll
    for (int j = 0; j < 32; j += 8)
        tile[ty + j][tx] = W[(size_t)(k0 + ty + j) * CC + n0 + tx];
    __syncthreads();
    #pragma unroll
    for (int j = 0; j < 32; j += 8) {
        float v = tile[tx][ty + j];
        __nv_bfloat16 h, l;
        split2(v, h, l);
        size_t o = (size_t)(n0 + ty + j) * CC + k0 + tx;
        dh[o] = h;
        dl[o] = l;
    }
}

// ---------------- HMMA bf16x3 GEMM, CTA tile 128M x 256N (R10 champion) ----------------
#define A_PLANE 16384               // 128 rows x 128B
#define B_PLANE 32768               // 256 rows x 128B
#define STAGE_BYTES (2 * A_PLANE + 2 * B_PLANE)     // 98304
#define GEMM_SMEM (2 * STAGE_BYTES)                 // 196608
#define OFF_AH 0
#define OFF_AL A_PLANE
#define OFF_BH (2*A_PLANE)
#define OFF_BL (2*A_PLANE + B_PLANE)
#define VT_STRIDE 136               // bf16 elems per col in V bounce buffer

extern __shared__ __align__(1024) char smg[];

__global__ void __launch_bounds__(256, 1)
gemm_bf16x3(const __nv_bfloat16* __restrict__ Ah, const __nv_bfloat16* __restrict__ Al,
            const __nv_bfloat16* __restrict__ Bh0, const __nv_bfloat16* __restrict__ Bl0,
            const __nv_bfloat16* __restrict__ Bh1, const __nv_bfloat16* __restrict__ Bl1,
            const __nv_bfloat16* __restrict__ Bh2, const __nv_bfloat16* __restrict__ Bl2,
            float* C0, float* C1) {
    const int tid = threadIdx.x;
    const int wid = tid >> 5;
    const int lane = tid & 31;
    const uint32_t sb = smem_u32(smg);
    const int nb = blockIdx.x * 256;
    const int mb = blockIdx.y * 128;
    const int z = blockIdx.z;
    const __nv_bfloat16* Bh = (z == 0) ? Bh0 : (z == 1) ? Bh1 : Bh2;
    const __nv_bfloat16* Bl = (z == 0) ? Bl0 : (z == 1) ? Bl1 : Bl2;

    const int wm = wid & 1;
    const int wn = wid >> 1;
    const int sub = lane >> 3;
    const int l7 = lane & 7;
    const uint32_t xorv = (uint32_t)l7 << 4;
    const int half_a = sub & 1;
    const int khalf = (sub >> 1) * 16;

    uint32_t a_row[4], b_row[4];
    #pragma unroll
    for (int mt = 0; mt < 4; ++mt)
        a_row[mt] = (uint32_t)(wm * 64 + mt * 16 + half_a * 8 + l7) * 128;
    #pragma unroll
    for (int nt = 0; nt < 4; ++nt)
        b_row[nt] = (uint32_t)(wn * 64 + nt * 16 + half_a * 8 + l7) * 128;

    float acc[4][8][4];
    #pragma unroll
    for (int i = 0; i < 4; ++i)
        #pragma unroll
        for (int j = 0; j < 8; ++j)
            #pragma unroll
            for (int r = 0; r < 4; ++r) acc[i][j][r] = 0.f;

    auto load_stage = [&](int it) {
        const uint32_t bbase = sb + (it & 1) * STAGE_BYTES;
        const size_t k0 = (size_t)it * 64;
        #pragma unroll
        for (int c = tid; c < 1024; c += 256) {
            const int row = c >> 3, ch = c & 7;
            const uint32_t soff = SMEM_SWZ((uint32_t)(row * 128 + ch * 16));
            const size_t aoff = (size_t)(mb + row) * CC + k0 + ch * 8;
            cp16(bbase + OFF_AH + soff, Ah + aoff);
            cp16(bbase + OFF_AL + soff, Al + aoff);
        }
        #pragma unroll
        for (int c = tid; c < 2048; c += 256) {
            const int row = c >> 3, ch = c & 7;
            const uint32_t soff = SMEM_SWZ((uint32_t)(row * 128 + ch * 16));
            const size_t boff = (size_t)(nb + row) * CC + k0 + ch * 8;
            cp16(bbase + OFF_BH + soff, Bh + boff);
            cp16(bbase + OFF_BL + soff, Bl + boff);
        }
        CP_COMMIT();
    };

    load_stage(0);

    for (int it = 0; it < 32; ++it) {
        if (it + 1 < 32) {
            load_stage(it + 1);   // prefetch in flight BEFORE waiting
            cp_wait<1>();
        } else {
            cp_wait<0>();
        }
        __syncthreads();

        const uint32_t base = sb + (it & 1) * STAGE_BYTES;
        #pragma unroll
        for (int ks = 0; ks < 4; ++ks) {
            const uint32_t col = (uint32_t)(ks * 32 + khalf) ^ xorv;

            uint32_t ah[4][4], al[4][4];
            #pragma unroll
            for (int mt = 0; mt < 4; ++mt) {
                ldm4(ah[mt][0], ah[mt][1], ah[mt][2], ah[mt][3],
                     base + OFF_AH + a_row[mt] + col);
                ldm4(al[mt][0], al[mt][1], al[mt][2], al[mt][3],
                     base + OFF_AL + a_row[mt] + col);
            }
            #pragma unroll
            for (int nt = 0; nt < 4; ++nt) {
                uint32_t bh0, bh1, bh2, bh3, bl0, bl1, bl2, bl3;
                ldm4(bh0, bh1, bh2, bh3, base + OFF_BH + b_row[nt] + col);
                ldm4(bl0, bl1, bl2, bl3, base + OFF_BL + b_row[nt] + col);
                #pragma unroll
                for (int mt = 0; mt < 4; ++mt) {
                    float* c0 = acc[mt][nt * 2];
                    float* c1 = acc[mt][nt * 2 + 1];
                    mma16816(c0[0], c0[1], c0[2], c0[3],
                             ah[mt][0], ah[mt][1], ah[mt][2], ah[mt][3], bh0, bh2);
                    mma16816(c1[0], c1[1], c1[2], c1[3],
                             ah[mt][0], ah[mt][1], ah[mt][2], ah[mt][3], bh1, bh3);
                    mma16816(c0[0], c0[1], c0[2], c0[3],
                             ah[mt][0], ah[mt][1], ah[mt][2], ah[mt][3], bl0, bl2);
                    mma16816(c1[0], c1[1], c1[2], c1[3],
                             ah[mt][0], ah[mt][1], ah[mt][2], ah[mt][3], bl1, bl3);
                    mma16816(c0[0], c0[1], c0[2], c0[3],
                             al[mt][0], al[mt][1], al[mt][2], al[mt][3], bh0, bh2);
                    mma16816(c1[0], c1[1], c1[2], c1[3],
                             al[mt][0], al[mt][1], al[mt][2], al[mt][3], bh1, bh3);
                }
            }
        }
        __syncthreads();
    }

    const int qrow = lane >> 2;
    const int qcol = (lane & 3) * 2;

    if (z != 2) {
        float* C = (z == 0) ? C0 : C1;
        #pragma unroll
        for (int mt = 0; mt < 4; ++mt) {
            const int row0 = mb + wm * 64 + mt * 16 + qrow;
            #pragma unroll
            for (int nt = 0; nt < 8; ++nt) {
                const int col = nb + wn * 64 + nt * 8 + qcol;
                float2 v0 = {acc[mt][nt][0], acc[mt][nt][1]};
                float2 v1 = {acc[mt][nt][2], acc[mt][nt][3]};
                *(float2*)(C + (size_t)row0 * CC + col)       = v0;
                *(float2*)(C + (size_t)(row0 + 8) * CC + col) = v1;
            }
        }
    } else {
        // V path: split to bf16 hi/lo, transpose via smem bounce, write [b,h][d][T]
        __nv_bfloat16* shh = (__nv_bfloat16*)smg;               // [256][VT_STRIDE]
        __nv_bfloat16* shl = shh + 256 * VT_STRIDE;
        #pragma unroll
        for (int mt = 0; mt < 4; ++mt) {
            const int r0 = wm * 64 + mt * 16 + qrow;
            #pragma unroll
            for (int nt = 0; nt < 8; ++nt) {
                const int cl = wn * 64 + nt * 8 + qcol;
                __nv_bfloat16 h, l;
                split2(acc[mt][nt][0], h, l);
                shh[cl * VT_STRIDE + r0] = h;       shl[cl * VT_STRIDE + r0] = l;
                split2(acc[mt][nt][1], h, l);
                shh[(cl + 1) * VT_STRIDE + r0] = h; shl[(cl + 1) * VT_STRIDE + r0] = l;
                split2(acc[mt][nt][2], h, l);
                shh[cl * VT_STRIDE + r0 + 8] = h;       shl[cl * VT_STRIDE + r0 + 8] = l;
                split2(acc[mt][nt][3], h, l);
                shh[(cl + 1) * VT_STRIDE + r0 + 8] = h; shl[(cl + 1) * VT_STRIDE + r0 + 8] = l;
            }
        }
        __syncthreads();
        const int b = mb >> 11;
        const int tloc = mb & (TT - 1);
        const int r = lane * 4;
        for (int ci = wid; ci < 256; ci += 8) {
            const int gcol = nb + ci;               // h*128 + d
            const int hh = gcol >> 7, d = gcol & 127;
            const size_t drow = ((size_t)(b * HH + hh) * DD + d) * TT + tloc;
            uint2 wh = *(uint2*)&shh[ci * VT_STRIDE + r];
            uint2 wl = *(uint2*)&shl[ci * VT_STRIDE + r];
            *(uint2*)(g_vth + drow + r) = wh;
            *(uint2*)(g_vtl + drow + r) = wl;
        }
    }
}

// ---------------- HMMA bf16x3 causal flash attention, 3-stage K/V pipeline ----------------
// smem: 3 stages of 64KB [KH|KL|VTH|VTL]. Q loaded into stages 1-2 region,
// extracted to fragments, then that region is reused by the ring.
#define SM_STG_BYTES 65536
#define ATT_SMEM2 (3 * SM_STG_BYTES)   // 196608
#define SM_Q 65536                     // QH at 65536, QL at 98304

extern __shared__ __align__(1024) char sma[];

__global__ void __launch_bounds__(256, 1) attn_hmma() {
    const int qb = (int)(gridDim.x - 1 - blockIdx.x);   // long CTAs launch first
    const int h  = blockIdx.y;
    const int b  = blockIdx.z;
    const int tid = threadIdx.x;
    const int wid = tid >> 5;
    const int lane = tid & 31;
    const uint32_t sb = smem_u32(sma);

    const int l7 = lane & 7;
    const int sub = lane >> 3;
    const int half_a = sub & 1;
    const int khalf = (sub >> 1) * 16;
    const uint32_t xorv = (uint32_t)l7 << 4;

    const size_t qrowbase = ((size_t)(b * TT + qb * 128)) * CC + h * DD;

    // load Q planes into [SM_Q, SM_Q+64K)
    #pragma unroll
    for (int c = tid; c < 2048; c += 256) {
        const int row = c >> 4;
        const int ch = c & 15;
        const int dch = ch >> 3, chi = ch & 7;
        const uint32_t soff = (uint32_t)dch * 16384 + SMEM_SWZ((uint32_t)(row * 128 + chi * 16));
        const size_t goff = qrowbase + (size_t)row * CC + dch * 64 + chi * 8;
        cp16(sb + SM_Q + soff, g_qh + goff);
        cp16(sb + SM_Q + 32768 + soff, g_ql + goff);
    }
    CP_COMMIT();

    const int kb_last = 2 * qb + 1;

    auto load_stage = [&](int kb) {
        const uint32_t base = sb + (uint32_t)(kb % 3) * SM_STG_BYTES;
        const size_t krow0 = ((size_t)(b * TT + kb * 64)) * CC + h * DD;
        #pragma unroll
        for (int c = tid; c < 1024; c += 256) {
            const int row = c >> 4;
            const int ch = c & 15;
            const int dch = ch >> 3, chi = ch & 7;
            const uint32_t soff = (uint32_t)dch * 8192 + SMEM_SWZ((uint32_t)(row * 128 + chi * 16));
            const size_t goff = krow0 + (size_t)row * CC + dch * 64 + chi * 8;
            cp16(base + 0 + soff, g_kh + goff);
            cp16(base + 16384 + soff, g_kl + goff);
        }
        const size_t vbase = ((size_t)((b * HH + h) * DD)) * TT + (size_t)kb * 64;
        #pragma unroll
        for (int c = tid; c < 1024; c += 256) {
            const int row = c >> 3;
            const int chi = c & 7;
            const uint32_t soff = SMEM_SWZ((uint32_t)(row * 128 + chi * 16));
            const size_t goff = vbase + (size_t)row * TT + chi * 8;
            cp16(base + 32768 + soff, g_vth + goff);
            cp16(base + 49152 + soff, g_vtl + goff);
        }
        CP_COMMIT();
    };

    load_stage(0);        // stage 0 buffer (does not overlap Q region)
    cp_wait<1>();         // Q arrived; stage 0 may still be in flight
    __syncthreads();

    // extract Q fragments from SM_Q region
    uint32_t qhf[8][4], qlf[8][4];
    {
        const uint32_t arow = (uint32_t)(wid * 16 + half_a * 8 + l7) * 128;
        #pragma unroll
        for (int kd = 0; kd < 8; ++kd) {
            const uint32_t col = (uint32_t)((kd & 3) * 32 + khalf) ^ xorv;
            const uint32_t off = (uint32_t)(kd >> 2) * 16384 + arow + col;
            ldm4(qhf[kd][0], qhf[kd][1], qhf[kd][2], qhf[kd][3], sb + SM_Q + off);
            ldm4(qlf[kd][0], qlf[kd][1], qlf[kd][2], qlf[kd][3], sb + SM_Q + 32768 + off);
        }
    }
    __syncthreads();      // all warps done reading Q region before it's overwritten
    load_stage(1);        // stage 1 = [65536,131072) : Q region, now safe

    float of[16][4];
    #pragma unroll
    for (int i = 0; i < 16; ++i)
        #pragma unroll
        for (int j = 0; j < 4; ++j) of[i][j] = 0.f;
    float mro0 = -1e30f, mro1 = -1e30f, lro0 = 0.f, lro1 = 0.f;

    const int row0g = qb * 128 + wid * 16 + (lane >> 2);
    const int colg0 = 2 * (lane & 3);

    for (int kb = 0; kb <= kb_last; ++kb) {
        // in flight before wait: {kb (maybe), kb+1 (if exists)}
        if (kb + 1 <= kb_last) cp_wait<1>();
        else cp_wait<0>();
        __syncthreads();                    // stage kb visible; all done with buffer (kb-1)%3
        if (kb + 2 <= kb_last) load_stage(kb + 2);   // writes (kb+2)%3 == (kb-1)%3 : safe

        const uint32_t base = sb + (uint32_t)(kb % 3) * SM_STG_BYTES;

        float sacc[8][4];
        #pragma unroll
        for (int nt = 0; nt < 8; ++nt)
            #pragma unroll
            for (int j = 0; j < 4; ++j) sacc[nt][j] = 0.f;

        #pragma unroll
        for (int kd = 0; kd < 8; ++kd) {
            const uint32_t col = (uint32_t)((kd & 3) * 32 + khalf) ^ xorv;
            const uint32_t chb = (uint32_t)(kd >> 2) * 8192;
            #pragma unroll
            for (int ntp = 0; ntp < 4; ++ntp) {
                const uint32_t rowb = (uint32_t)(ntp * 16 + half_a * 8 + l7) * 128;
                uint32_t kh0, kh1, kh2, kh3, kl0, kl1, kl2, kl3;
                ldm4(kh0, kh1, kh2, kh3, base + chb + rowb + col);
                ldm4(kl0, kl1, kl2, kl3, base + 16384 + chb + rowb + col);
                float* c0 = sacc[ntp * 2];
                float* c1 = sacc[ntp * 2 + 1];
                mma16816(c0[0], c0[1], c0[2], c0[3],
                         qhf[kd][0], qhf[kd][1], qhf[kd][2], qhf[kd][3], kh0, kh2);
                mma16816(c1[0], c1[1], c1[2], c1[3],
                         qhf[kd][0], qhf[kd][1], qhf[kd][2], qhf[kd][3], kh1, kh3);
                mma16816(c0[0], c0[1], c0[2], c0[3],
                         qhf[kd][0], qhf[kd][1], qhf[kd][2], qhf[kd][3], kl0, kl2);
                mma16816(c1[0], c1[1], c1[2], c1[3],
                         qhf[kd][0], qhf[kd][1], qhf[kd][2], qhf[kd][3], kl1, kl3);
                mma16816(c0[0], c0[1], c0[2], c0[3],
                         qlf[kd][0], qlf[kd][1], qlf[kd][2], qlf[kd][3], kh0, kh2);
                mma16816(c1[0], c1[1], c1[2], c1[3],
                         qlf[kd][0], qlf[kd][1], qlf[kd][2], qlf[kd][3], kh1, kh3);
            }
        }

        if (kb * 64 + 63 > qb * 128 + wid * 16) {
            const int cb = kb * 64 + colg0;
            #pragma unroll
            for (int nt = 0; nt < 8; ++nt) {
                const int c0 = cb + nt * 8, c1 = c0 + 1;
                if (c0 > row0g) sacc[nt][0] = -1e30f;
                if (c1 > row0g) sacc[nt][1] = -1e30f;
                if (c0 > row0g + 8) sacc[nt][2] = -1e30f;
                if (c1 > row0g + 8) sacc[nt][3] = -1e30f;
            }
        }

        float mx0 = -1e30f, mx1 = -1e30f;
        #pragma unroll
        for (int nt = 0; nt < 8; ++nt) {
            mx0 = fmaxf(mx0, fmaxf(sacc[nt][0], sacc[nt][1]));
            mx1 = fmaxf(mx1, fmaxf(sacc[nt][2], sacc[nt][3]));
        }
        mx0 = fmaxf(mx0, __shfl_xor_sync(0xffffffffu, mx0, 1));
        mx0 = fmaxf(mx0, __shfl_xor_sync(0xffffffffu, mx0, 2));
        mx1 = fmaxf(mx1, __shfl_xor_sync(0xffffffffu, mx1, 1));
        mx1 = fmaxf(mx1, __shfl_xor_sync(0xffffffffu, mx1, 2));

        const float mn0 = fmaxf(mro0, mx0);
        const float mn1 = fmaxf(mro1, mx1);
        const float al0 = __expf(mro0 - mn0);
        const float al1 = __expf(mro1 - mn1);
        mro0 = mn0; mro1 = mn1;

        float rs0 = 0.f, rs1 = 0.f;
        #pragma unroll
        for (int nt = 0; nt < 8; ++nt) {
            float p0 = __expf(sacc[nt][0] - mn0);
            float p1 = __expf(sacc[nt][1] - mn0);
            float p2 = __expf(sacc[nt][2] - mn1);
            float p3 = __expf(sacc[nt][3] - mn1);
            sacc[nt][0] = p0; sacc[nt][1] = p1; sacc[nt][2] = p2; sacc[nt][3] = p3;
            rs0 += p0 + p1;
            rs1 += p2 + p3;
        }
        rs0 += __shfl_xor_sync(0xffffffffu, rs0, 1);
        rs0 += __shfl_xor_sync(0xffffffffu, rs0, 2);
        rs1 += __shfl_xor_sync(0xffffffffu, rs1, 1);
        rs1 += __shfl_xor_sync(0xffffffffu, rs1, 2);
        lro0 = lro0 * al0 + rs0;
        lro1 = lro1 * al1 + rs1;

        #pragma unroll
        for (int dt = 0; dt < 16; ++dt) {
            of[dt][0] *= al0; of[dt][1] *= al0;
            of[dt][2] *= al1; of[dt][3] *= al1;
        }

        uint32_t pah[4][4], pal[4][4];
        #pragma unroll
        for (int g = 0; g < 4; ++g) {
            const float* pe = sacc[2 * g];
            const float* po = sacc[2 * g + 1];
            pah[g][0] = packbf2(pe[0], pe[1]);
            pah[g][1] = packbf2(pe[2], pe[3]);
            pah[g][2] = packbf2(po[0], po[1]);
            pah[g][3] = packbf2(po[2], po[3]);
            __nv_bfloat162* bh;
            bh = (__nv_bfloat162*)&pah[g][0];
            pal[g][0] = packbf2(pe[0] - __bfloat162float(bh->x), pe[1] - __bfloat162float(bh->y));
            bh = (__nv_bfloat162*)&pah[g][1];
            pal[g][1] = packbf2(pe[2] - __bfloat162float(bh->x), pe[3] - __bfloat162float(bh->y));
            bh = (__nv_bfloat162*)&pah[g][2];
            pal[g][2] = packbf2(po[0] - __bfloat162float(bh->x), po[1] - __bfloat162float(bh->y));
            bh = (__nv_bfloat162*)&pah[g][3];
            pal[g][3] = packbf2(po[2] - __bfloat162float(bh->x), po[3] - __bfloat162float(bh->y));
        }

        #pragma unroll
        for (int g = 0; g < 4; ++g) {
            const uint32_t col = (uint32_t)(g * 32 + khalf) ^ xorv;
            #pragma unroll
            for (int dt = 0; dt < 8; ++dt) {
                const uint32_t rowb = (uint32_t)(dt * 16 + half_a * 8 + l7) * 128;
                uint32_t vh0, vh1, vh2, vh3, vl0, vl1, vl2, vl3;
                ldm4(vh0, vh1, vh2, vh3, base + 32768 + rowb + col);
                ldm4(vl0, vl1, vl2, vl3, base + 49152 + rowb + col);
                float* o0 = of[dt * 2];
                float* o1 = of[dt * 2 + 1];
                mma16816(o0[0], o0[1], o0[2], o0[3],
                         pah[g][0], pah[g][1], pah[g][2], pah[g][3], vh0, vh2);
                mma16816(o1[0], o1[1], o1[2], o1[3],
                         pah[g][0], pah[g][1], pah[g][2], pah[g][3], vh1, vh3);
                mma16816(o0[0], o0[1], o0[2], o0[3],
                         pah[g][0], pah[g][1], pah[g][2], pah[g][3], vl0, vl2);
                mma16816(o1[0], o1[1], o1[2], o1[3],
                         pah[g][0], pah[g][1], pah[g][2], pah[g][3], vl1, vl3);
                mma16816(o0[0], o0[1], o0[2], o0[3],
                         pal[g][0], pal[g][1], pal[g][2], pal[g][3], vh0, vh2);
                mma16816(o1[0], o1[1], o1[2], o1[3],
                         pal[g][0], pal[g][1], pal[g][2], pal[g][3], vh1, vh3);
            }
        }
    }

    // ---- epilogue: write bf16 hi/lo planes for the O-projection directly ----
    const float inv0 = 1.f / lro0;
    const float inv1 = 1.f / lro1;
    const size_t obase = qrowbase + (size_t)(wid * 16 + (lane >> 2)) * CC + colg0;
    #pragma unroll
    for (int dt = 0; dt < 16; ++dt) {
        float v00 = of[dt][0] * inv0, v01 = of[dt][1] * inv0;
        float v10 = of[dt][2] * inv1, v11 = of[dt][3] * inv1;
        __nv_bfloat16 h0, l0, h1, l1;
        split2(v00, h0, l0); split2(v01, h1, l1);
        *(__nv_bfloat162*)(g_yh + obase + dt * 8) = __nv_bfloat162(h0, h1);
        *(__nv_bfloat162*)(g_yl + obase + dt * 8) = __nv_bfloat162(l0, l1);
        split2(v10, h0, l0); split2(v11, h1, l1);
        *(__nv_bfloat162*)(g_yh + obase + 8 * CC + dt * 8) = __nv_bfloat162(h0, h1);
        *(__nv_bfloat162*)(g_yl + obase + 8 * CC + dt * 8) = __nv_bfloat162(l0, l1);
    }
}

// ---------------- launch ----------------
extern "C" void kernel_launch(void* const* d_in, const int* in_sizes, int n_in,
                              void* d_out, int out_size) {
    const float* x  = (const float*)d_in[0];
    const float* wq = (const float*)d_in[1];
    const float* wk = (const float*)d_in[2];
    const float* wv = (const float*)d_in[3];
    const float* wo = (const float*)d_in[4];
    float* out = (float*)d_out;

    float *q, *k;
    cudaGetSymbolAddress((void**)&q, g_q);
    cudaGetSymbolAddress((void**)&k, g_k);

    __nv_bfloat16 *xh, *xl, *yh, *yl;
    __nv_bfloat16 *wqh, *wql, *wkh, *wkl, *wvh, *wvl, *woh, *wol;
    cudaGetSymbolAddress((void**)&xh, g_xh);   cudaGetSymbolAddress((void**)&xl, g_xl);
    cudaGetSymbolAddress((void**)&yh, g_yh);   cudaGetSymbolAddress((void**)&yl, g_yl);
    cudaGetSymbolAddress((void**)&wqh, g_wqh); cudaGetSymbolAddress((void**)&wql, g_wql);
    cudaGetSymbolAddress((void**)&wkh, g_wkh); cudaGetSymbolAddress((void**)&wkl, g_wkl);
    cudaGetSymbolAddress((void**)&wvh, g_wvh); cudaGetSymbolAddress((void**)&wvl, g_wvl);
    cudaGetSymbolAddress((void**)&woh, g_woh); cudaGetSymbolAddress((void**)&wol, g_wol);

    rope_table_kernel<<<512, 256>>>();
    conv_split_kernel<<<(MM * CC) / 1024, 256>>>(x, xh, xl);
    conv_w4_kernel<<<dim3(CC / 32, CC / 32, 4), dim3(32, 8)>>>(wq, wk, wv, wo);

    cudaFuncSetAttribute(gemm_bf16x3, cudaFuncAttributeMaxDynamicSharedMemorySize, GEMM_SMEM);

    // fused QKV projection; z==2 (V) writes transposed bf16 planes directly
    gemm_bf16x3<<<dim3(CC / 256, MM / 128, 3), 256, GEMM_SMEM>>>(
        xh, xl, wqh, wql, wkh, wkl, wvh, wvl, q, k);

    rope_apply_split_kernel<<<(BB * TT * HH * 32) / 256, 256>>>();

    cudaFuncSetAttribute(attn_hmma, cudaFuncAttributeMaxDynamicSharedMemorySize, ATT_SMEM2);
    attn_hmma<<<dim3(TT / 128, HH, BB), 256, ATT_SMEM2>>>();

    // output projection (z==0 path, C0 = out)
    gemm_bf16x3<<<dim3(CC / 256, MM / 128, 1), 256, GEMM_SMEM>>>(
        yh, yl, woh, wol, woh, wol, woh, wol, out, out);
}

// round 15
// speedup vs baseline: 1.2080x; 1.1172x over previous
#include <cuda_runtime.h>
#include <cuda_bf16.h>
#include <math.h>
#include <stdint.h>

#define BB 2
#define TT 2048
#define CC 2048
#define HH 16
#define DD 128
#define MM (BB*TT)   // 4096
#define ATT_SCALE 0.08838834764831845f

// ---------------- scratch (static device globals; no allocation) ----------------
__device__ float g_q[MM*CC];
__device__ float g_k[MM*CC];
__device__ float g_cos[TT*64];
__device__ float g_sin[TT*64];

// bf16 split planes
__device__ __nv_bfloat16 g_xh[MM*CC], g_xl[MM*CC];
__device__ __nv_bfloat16 g_yh[MM*CC], g_yl[MM*CC];
__device__ __nv_bfloat16 g_wqh[CC*CC], g_wql[CC*CC];
__device__ __nv_bfloat16 g_wkh[CC*CC], g_wkl[CC*CC];
__device__ __nv_bfloat16 g_wvh[CC*CC], g_wvl[CC*CC];
__device__ __nv_bfloat16 g_woh[CC*CC], g_wol[CC*CC];
// attention operand planes
__device__ __nv_bfloat16 g_qh[MM*CC], g_ql[MM*CC];   // RoPE'd, scaled
__device__ __nv_bfloat16 g_kh[MM*CC], g_kl[MM*CC];   // RoPE'd
__device__ __nv_bfloat16 g_vth[MM*CC], g_vtl[MM*CC]; // V transposed: [b,h][d][T]

// ================= helpers =================
__device__ __forceinline__ uint32_t smem_u32(const void* p) {
    uint32_t a;
    asm("{ .reg .u64 t; cvta.to.shared.u64 t, %1; cvt.u32.u64 %0, t; }" : "=r"(a) : "l"(p));
    return a;
}
#define SMEM_SWZ(o) ((o) ^ (((o) >> 3) & 0x70))

__device__ __forceinline__ void cp16(uint32_t dst, const void* src) {
    asm volatile("cp.async.cg.shared.global [%0], [%1], 16;" :: "r"(dst), "l"(src));
}
#define CP_COMMIT() asm volatile("cp.async.commit_group;" ::: "memory")
template<int N> __device__ __forceinline__ void cp_wait() {
    asm volatile("cp.async.wait_group %0;" :: "n"(N) : "memory");
}

__device__ __forceinline__ void ldm4(uint32_t& r0, uint32_t& r1, uint32_t& r2, uint32_t& r3,
                                     uint32_t addr) {
    asm volatile("ldmatrix.sync.aligned.m8n8.x4.shared.b16 {%0,%1,%2,%3}, [%4];"
                 : "=r"(r0), "=r"(r1), "=r"(r2), "=r"(r3) : "r"(addr));
}
__device__ __forceinline__ void mma16816(float& c0, float& c1, float& c2, float& c3,
                                         uint32_t a0, uint32_t a1, uint32_t a2, uint32_t a3,
                                         uint32_t b0, uint32_t b1) {
    asm volatile("mma.sync.aligned.m16n8k16.row.col.f32.bf16.bf16.f32 "
                 "{%0,%1,%2,%3}, {%4,%5,%6,%7}, {%8,%9}, {%0,%1,%2,%3};"
                 : "+f"(c0), "+f"(c1), "+f"(c2), "+f"(c3)
                 : "r"(a0), "r"(a1), "r"(a2), "r"(a3), "r"(b0), "r"(b1));
}

__device__ __forceinline__ void split2(float v, __nv_bfloat16& h, __nv_bfloat16& l) {
    h = __float2bfloat16(v);
    l = __float2bfloat16(v - __bfloat162float(h));
}
__device__ __forceinline__ uint32_t packbf2(float lo, float hi) {
    __nv_bfloat162 t = __floats2bfloat162_rn(lo, hi);
    return *(uint32_t*)&t;
}

// ---------------- RoPE tables ----------------
__global__ void __launch_bounds__(256) rope_table_kernel() {
    int idx = blockIdx.x * 256 + threadIdx.x;
    if (idx >= TT * 64) return;
    int t = idx >> 6, i = idx & 63;
    double invf = exp(-((double)(2 * i) / 128.0) * log(10000.0));
    double ang = (double)t * invf;
    double sn, cs;
    sincos(ang, &sn, &cs);
    g_cos[idx] = (float)cs;
    g_sin[idx] = (float)sn;
}

// ---------------- RoPE apply + bf16 split (Q scaled), 2x vectorized ----------------
__global__ void __launch_bounds__(256) rope_apply_split_kernel() {
    int idx = blockIdx.x * 256 + threadIdx.x;
    int p = idx & 31;
    int h = (idx >> 5) & (HH - 1);
    int t = (idx >> 9) & (TT - 1);
    int b = idx >> 20;
    int i2 = p * 2;
    size_t base = ((size_t)(b * TT + t)) * CC + h * DD;
    float2 c = *(const float2*)&g_cos[t * 64 + i2];
    float2 s = *(const float2*)&g_sin[t * 64 + i2];
    float2 qa = *(const float2*)&g_q[base + i2];
    float2 qb = *(const float2*)&g_q[base + 64 + i2];
    float2 ka = *(const float2*)&g_k[base + i2];
    float2 kb = *(const float2*)&g_k[base + 64 + i2];

    float qr0x = (qa.x * c.x - qb.x * s.x) * ATT_SCALE;
    float qr0y = (qa.y * c.y - qb.y * s.y) * ATT_SCALE;
    float qr1x = (qb.x * c.x + qa.x * s.x) * ATT_SCALE;
    float qr1y = (qb.y * c.y + qa.y * s.y) * ATT_SCALE;
    float kr0x = ka.x * c.x - kb.x * s.x;
    float kr0y = ka.y * c.y - kb.y * s.y;
    float kr1x = kb.x * c.x + ka.x * s.x;
    float kr1y = kb.y * c.y + ka.y * s.y;

    __nv_bfloat16 h0, l0, h1, l1;
    split2(qr0x, h0, l0); split2(qr0y, h1, l1);
    *(__nv_bfloat162*)&g_qh[base + i2] = __nv_bfloat162(h0, h1);
    *(__nv_bfloat162*)&g_ql[base + i2] = __nv_bfloat162(l0, l1);
    split2(qr1x, h0, l0); split2(qr1y, h1, l1);
    *(__nv_bfloat162*)&g_qh[base + 64 + i2] = __nv_bfloat162(h0, h1);
    *(__nv_bfloat162*)&g_ql[base + 64 + i2] = __nv_bfloat162(l0, l1);
    split2(kr0x, h0, l0); split2(kr0y, h1, l1);
    *(__nv_bfloat162*)&g_kh[base + i2] = __nv_bfloat162(h0, h1);
    *(__nv_bfloat162*)&g_kl[base + i2] = __nv_bfloat162(l0, l1);
    split2(kr1x, h0, l0); split2(kr1y, h1, l1);
    *(__nv_bfloat162*)&g_kh[base + 64 + i2] = __nv_bfloat162(h0, h1);
    *(__nv_bfloat162*)&g_kl[base + 64 + i2] = __nv_bfloat162(l0, l1);
}

// ---------------- plain split, 4x vectorized ----------------
__global__ void __launch_bounds__(256) conv_split_kernel(const float* __restrict__ src,
                                                         __nv_bfloat16* __restrict__ dh,
                                                         __nv_bfloat16* __restrict__ dl) {
    int i4 = (blockIdx.x * 256 + threadIdx.x) * 4;
    float4 v = *(const float4*)(src + i4);
    __nv_bfloat16 h0, l0, h1, l1, h2, l2, h3, l3;
    split2(v.x, h0, l0); split2(v.y, h1, l1);
    split2(v.z, h2, l2); split2(v.w, h3, l3);
    *(__nv_bfloat162*)&dh[i4]     = __nv_bfloat162(h0, h1);
    *(__nv_bfloat162*)&dh[i4 + 2] = __nv_bfloat162(h2, h3);
    *(__nv_bfloat162*)&dl[i4]     = __nv_bfloat162(l0, l1);
    *(__nv_bfloat162*)&dl[i4 + 2] = __nv_bfloat162(l2, l3);
}

// W[K,N] fp32 -> Wt_hi/lo[N,K] bf16 (transpose + split); z selects weight
__global__ void __launch_bounds__(256) conv_w4_kernel(const float* __restrict__ W0,
                                                      const float* __restrict__ W1,
                                                      const float* __restrict__ W2,
                                                      const float* __restrict__ W3) {
    __shared__ float tile[32][33];
    const int z = blockIdx.z;
    const float* W = (z == 0) ? W0 : (z == 1) ? W1 : (z == 2) ? W2 : W3;
    __nv_bfloat16* dh = (z == 0) ? g_wqh : (z == 1) ? g_wkh : (z == 2) ? g_wvh : g_woh;
    __nv_bfloat16* dl = (z == 0) ? g_wql : (z == 1) ? g_wkl : (z == 2) ? g_wvl : g_wol;
    int tx = threadIdx.x, ty = threadIdx.y;
    int n0 = blockIdx.x * 32, k0 = blockIdx.y * 32;
    #pragma unroll
    for (int j = 0; j < 32; j += 8)
        tile[ty + j][tx] = W[(size_t)(k0 + ty + j) * CC + n0 + tx];
    __syncthreads();
    #pragma unroll
    for (int j = 0; j < 32; j += 8) {
        float v = tile[tx][ty + j];
        __nv_bfloat16 h, l;
        split2(v, h, l);
        size_t o = (size_t)(n0 + ty + j) * CC + k0 + tx;
        dh[o] = h;
        dl[o] = l;
    }
}

// ---------------- HMMA bf16x3 GEMM, CTA tile 64M x 128N, 2 CTAs/SM ----------------
// 8 warps as 2m x 4n, warp tile 32x32. K-chunk 64, 2 stages of 48KB.
#define A_PLANE2 8192               // 64 rows x 128B
#define B_PLANE2 16384              // 128 rows x 128B
#define STAGE2 (2 * A_PLANE2 + 2 * B_PLANE2)        // 49152
#define GEMM_SMEM (2 * STAGE2)                      // 98304
#define OFF_AH 0
#define OFF_AL A_PLANE2
#define OFF_BH (2*A_PLANE2)
#define OFF_BL (2*A_PLANE2 + B_PLANE2)
#define VT2_STRIDE 72               // bf16 elems per col in V bounce buffer

extern __shared__ __align__(1024) char smg[];

__global__ void __launch_bounds__(256, 2)
gemm_bf16x3(const __nv_bfloat16* __restrict__ Ah, const __nv_bfloat16* __restrict__ Al,
            const __nv_bfloat16* __restrict__ Bh0, const __nv_bfloat16* __restrict__ Bl0,
            const __nv_bfloat16* __restrict__ Bh1, const __nv_bfloat16* __restrict__ Bl1,
            const __nv_bfloat16* __restrict__ Bh2, const __nv_bfloat16* __restrict__ Bl2,
            float* C0, float* C1) {
    const int tid = threadIdx.x;
    const int wid = tid >> 5;
    const int lane = tid & 31;
    const uint32_t sb = smem_u32(smg);
    const int nb = blockIdx.x * 128;
    const int mb = blockIdx.y * 64;
    const int z = blockIdx.z;
    const __nv_bfloat16* Bh = (z == 0) ? Bh0 : (z == 1) ? Bh1 : Bh2;
    const __nv_bfloat16* Bl = (z == 0) ? Bl0 : (z == 1) ? Bl1 : Bl2;

    const int wm = wid & 1;          // 0..1 (m, 32 rows)
    const int wn = wid >> 1;         // 0..3 (n, 32 cols)
    const int sub = lane >> 3;
    const int l7 = lane & 7;
    const uint32_t xorv = (uint32_t)l7 << 4;
    const int half_a = sub & 1;
    const int khalf = (sub >> 1) * 16;

    uint32_t a_row[2], b_row[2];
    #pragma unroll
    for (int mt = 0; mt < 2; ++mt)
        a_row[mt] = (uint32_t)(wm * 32 + mt * 16 + half_a * 8 + l7) * 128;
    #pragma unroll
    for (int nt = 0; nt < 2; ++nt)
        b_row[nt] = (uint32_t)(wn * 32 + nt * 16 + half_a * 8 + l7) * 128;

    float acc[2][4][4];
    #pragma unroll
    for (int i = 0; i < 2; ++i)
        #pragma unroll
        for (int j = 0; j < 4; ++j)
            #pragma unroll
            for (int r = 0; r < 4; ++r) acc[i][j][r] = 0.f;

    auto load_stage = [&](int it) {
        const uint32_t bbase = sb + (it & 1) * STAGE2;
        const size_t k0 = (size_t)it * 64;
        #pragma unroll
        for (int c = tid; c < 512; c += 256) {      // A: 64 rows x 8 chunks
            const int row = c >> 3, ch = c & 7;
            const uint32_t soff = SMEM_SWZ((uint32_t)(row * 128 + ch * 16));
            const size_t aoff = (size_t)(mb + row) * CC + k0 + ch * 8;
            cp16(bbase + OFF_AH + soff, Ah + aoff);
            cp16(bbase + OFF_AL + soff, Al + aoff);
        }
        #pragma unroll
        for (int c = tid; c < 1024; c += 256) {     // B: 128 rows x 8 chunks
            const int row = c >> 3, ch = c & 7;
            const uint32_t soff = SMEM_SWZ((uint32_t)(row * 128 + ch * 16));
            const size_t boff = (size_t)(nb + row) * CC + k0 + ch * 8;
            cp16(bbase + OFF_BH + soff, Bh + boff);
            cp16(bbase + OFF_BL + soff, Bl + boff);
        }
        CP_COMMIT();
    };

    load_stage(0);

    for (int it = 0; it < 32; ++it) {
        if (it + 1 < 32) {
            load_stage(it + 1);   // prefetch in flight BEFORE waiting
            cp_wait<1>();
        } else {
            cp_wait<0>();
        }
        __syncthreads();

        const uint32_t base = sb + (it & 1) * STAGE2;
        #pragma unroll
        for (int ks = 0; ks < 4; ++ks) {
            const uint32_t col = (uint32_t)(ks * 32 + khalf) ^ xorv;

            uint32_t ah[2][4], al[2][4];
            #pragma unroll
            for (int mt = 0; mt < 2; ++mt) {
                ldm4(ah[mt][0], ah[mt][1], ah[mt][2], ah[mt][3],
                     base + OFF_AH + a_row[mt] + col);
                ldm4(al[mt][0], al[mt][1], al[mt][2], al[mt][3],
                     base + OFF_AL + a_row[mt] + col);
            }
            #pragma unroll
            for (int nt = 0; nt < 2; ++nt) {
                uint32_t bh0, bh1, bh2, bh3, bl0, bl1, bl2, bl3;
                ldm4(bh0, bh1, bh2, bh3, base + OFF_BH + b_row[nt] + col);
                ldm4(bl0, bl1, bl2, bl3, base + OFF_BL + b_row[nt] + col);
                #pragma unroll
                for (int mt = 0; mt < 2; ++mt) {
                    float* c0 = acc[mt][nt * 2];
                    float* c1 = acc[mt][nt * 2 + 1];
                    mma16816(c0[0], c0[1], c0[2], c0[3],
                             ah[mt][0], ah[mt][1], ah[mt][2], ah[mt][3], bh0, bh2);
                    mma16816(c1[0], c1[1], c1[2], c1[3],
                             ah[mt][0], ah[mt][1], ah[mt][2], ah[mt][3], bh1, bh3);
                    mma16816(c0[0], c0[1], c0[2], c0[3],
                             ah[mt][0], ah[mt][1], ah[mt][2], ah[mt][3], bl0, bl2);
                    mma16816(c1[0], c1[1], c1[2], c1[3],
                             ah[mt][0], ah[mt][1], ah[mt][2], ah[mt][3], bl1, bl3);
                    mma16816(c0[0], c0[1], c0[2], c0[3],
                             al[mt][0], al[mt][1], al[mt][2], al[mt][3], bh0, bh2);
                    mma16816(c1[0], c1[1], c1[2], c1[3],
                             al[mt][0], al[mt][1], al[mt][2], al[mt][3], bh1, bh3);
                }
            }
        }
        __syncthreads();
    }

    const int qrow = lane >> 2;
    const int qcol = (lane & 3) * 2;

    if (z != 2) {
        float* C = (z == 0) ? C0 : C1;
        #pragma unroll
        for (int mt = 0; mt < 2; ++mt) {
            const int row0 = mb + wm * 32 + mt * 16 + qrow;
            #pragma unroll
            for (int nt = 0; nt < 4; ++nt) {
                const int col = nb + wn * 32 + nt * 8 + qcol;
                float2 v0 = {acc[mt][nt][0], acc[mt][nt][1]};
                float2 v1 = {acc[mt][nt][2], acc[mt][nt][3]};
                *(float2*)(C + (size_t)row0 * CC + col)       = v0;
                *(float2*)(C + (size_t)(row0 + 8) * CC + col) = v1;
            }
        }
    } else {
        // V path: split to bf16 hi/lo, transpose via smem bounce, write [b,h][d][T]
        __nv_bfloat16* shh = (__nv_bfloat16*)smg;               // [128][VT2_STRIDE]
        __nv_bfloat16* shl = shh + 128 * VT2_STRIDE;
        #pragma unroll
        for (int mt = 0; mt < 2; ++mt) {
            const int r0 = wm * 32 + mt * 16 + qrow;
            #pragma unroll
            for (int nt = 0; nt < 4; ++nt) {
                const int cl = wn * 32 + nt * 8 + qcol;
                __nv_bfloat16 h, l;
                split2(acc[mt][nt][0], h, l);
                shh[cl * VT2_STRIDE + r0] = h;       shl[cl * VT2_STRIDE + r0] = l;
                split2(acc[mt][nt][1], h, l);
                shh[(cl + 1) * VT2_STRIDE + r0] = h; shl[(cl + 1) * VT2_STRIDE + r0] = l;
                split2(acc[mt][nt][2], h, l);
                shh[cl * VT2_STRIDE + r0 + 8] = h;       shl[cl * VT2_STRIDE + r0 + 8] = l;
                split2(acc[mt][nt][3], h, l);
                shh[(cl + 1) * VT2_STRIDE + r0 + 8] = h; shl[(cl + 1) * VT2_STRIDE + r0 + 8] = l;
            }
        }
        __syncthreads();
        const int b = mb >> 11;
        const int tloc = mb & (TT - 1);
        const int r = lane * 2;
        for (int ci = wid; ci < 128; ci += 8) {
            const int gcol = nb + ci;               // h*128 + d
            const int hh = gcol >> 7, d = gcol & 127;
            const size_t drow = ((size_t)(b * HH + hh) * DD + d) * TT + tloc;
            uint32_t wh = *(uint32_t*)&shh[ci * VT2_STRIDE + r];
            uint32_t wl = *(uint32_t*)&shl[ci * VT2_STRIDE + r];
            *(uint32_t*)(g_vth + drow + r) = wh;
            *(uint32_t*)(g_vtl + drow + r) = wl;
        }
    }
}

// ---------------- HMMA bf16x3 causal flash attention, 3-stage K/V pipeline ----------------
#define SM_STG_BYTES 65536
#define ATT_SMEM2 (3 * SM_STG_BYTES)   // 196608
#define SM_Q 65536

extern __shared__ __align__(1024) char sma[];

__global__ void __launch_bounds__(256, 1) attn_hmma() {
    const int qb = (int)(gridDim.x - 1 - blockIdx.x);   // long CTAs launch first
    const int h  = blockIdx.y;
    const int b  = blockIdx.z;
    const int tid = threadIdx.x;
    const int wid = tid >> 5;
    const int lane = tid & 31;
    const uint32_t sb = smem_u32(sma);

    const int l7 = lane & 7;
    const int sub = lane >> 3;
    const int half_a = sub & 1;
    const int khalf = (sub >> 1) * 16;
    const uint32_t xorv = (uint32_t)l7 << 4;

    const size_t qrowbase = ((size_t)(b * TT + qb * 128)) * CC + h * DD;

    #pragma unroll
    for (int c = tid; c < 2048; c += 256) {
        const int row = c >> 4;
        const int ch = c & 15;
        const int dch = ch >> 3, chi = ch & 7;
        const uint32_t soff = (uint32_t)dch * 16384 + SMEM_SWZ((uint32_t)(row * 128 + chi * 16));
        const size_t goff = qrowbase + (size_t)row * CC + dch * 64 + chi * 8;
        cp16(sb + SM_Q + soff, g_qh + goff);
        cp16(sb + SM_Q + 32768 + soff, g_ql + goff);
    }
    CP_COMMIT();

    const int kb_last = 2 * qb + 1;

    auto load_stage = [&](int kb) {
        const uint32_t base = sb + (uint32_t)(kb % 3) * SM_STG_BYTES;
        const size_t krow0 = ((size_t)(b * TT + kb * 64)) * CC + h * DD;
        #pragma unroll
        for (int c = tid; c < 1024; c += 256) {
            const int row = c >> 4;
            const int ch = c & 15;
            const int dch = ch >> 3, chi = ch & 7;
            const uint32_t soff = (uint32_t)dch * 8192 + SMEM_SWZ((uint32_t)(row * 128 + chi * 16));
            const size_t goff = krow0 + (size_t)row * CC + dch * 64 + chi * 8;
            cp16(base + 0 + soff, g_kh + goff);
            cp16(base + 16384 + soff, g_kl + goff);
        }
        const size_t vbase = ((size_t)((b * HH + h) * DD)) * TT + (size_t)kb * 64;
        #pragma unroll
        for (int c = tid; c < 1024; c += 256) {
            const int row = c >> 3;
            const int chi = c & 7;
            const uint32_t soff = SMEM_SWZ((uint32_t)(row * 128 + chi * 16));
            const size_t goff = vbase + (size_t)row * TT + chi * 8;
            cp16(base + 32768 + soff, g_vth + goff);
            cp16(base + 49152 + soff, g_vtl + goff);
        }
        CP_COMMIT();
    };

    load_stage(0);
    cp_wait<1>();
    __syncthreads();

    uint32_t qhf[8][4], qlf[8][4];
    {
        const uint32_t arow = (uint32_t)(wid * 16 + half_a * 8 + l7) * 128;
        #pragma unroll
        for (int kd = 0; kd < 8; ++kd) {
            const uint32_t col = (uint32_t)((kd & 3) * 32 + khalf) ^ xorv;
            const uint32_t off = (uint32_t)(kd >> 2) * 16384 + arow + col;
            ldm4(qhf[kd][0], qhf[kd][1], qhf[kd][2], qhf[kd][3], sb + SM_Q + off);
            ldm4(qlf[kd][0], qlf[kd][1], qlf[kd][2], qlf[kd][3], sb + SM_Q + 32768 + off);
        }
    }
    __syncthreads();
    load_stage(1);

    float of[16][4];
    #pragma unroll
    for (int i = 0; i < 16; ++i)
        #pragma unroll
        for (int j = 0; j < 4; ++j) of[i][j] = 0.f;
    float mro0 = -1e30f, mro1 = -1e30f, lro0 = 0.f, lro1 = 0.f;

    const int row0g = qb * 128 + wid * 16 + (lane >> 2);
    const int colg0 = 2 * (lane & 3);

    for (int kb = 0; kb <= kb_last; ++kb) {
        if (kb + 1 <= kb_last) cp_wait<1>();
        else cp_wait<0>();
        __syncthreads();
        if (kb + 2 <= kb_last) load_stage(kb + 2);

        const uint32_t base = sb + (uint32_t)(kb % 3) * SM_STG_BYTES;

        float sacc[8][4];
        #pragma unroll
        for (int nt = 0; nt < 8; ++nt)
            #pragma unroll
            for (int j = 0; j < 4; ++j) sacc[nt][j] = 0.f;

        #pragma unroll
        for (int kd = 0; kd < 8; ++kd) {
            const uint32_t col = (uint32_t)((kd & 3) * 32 + khalf) ^ xorv;
            const uint32_t chb = (uint32_t)(kd >> 2) * 8192;
            #pragma unroll
            for (int ntp = 0; ntp < 4; ++ntp) {
                const uint32_t rowb = (uint32_t)(ntp * 16 + half_a * 8 + l7) * 128;
                uint32_t kh0, kh1, kh2, kh3, kl0, kl1, kl2, kl3;
                ldm4(kh0, kh1, kh2, kh3, base + chb + rowb + col);
                ldm4(kl0, kl1, kl2, kl3, base + 16384 + chb + rowb + col);
                float* c0 = sacc[ntp * 2];
                float* c1 = sacc[ntp * 2 + 1];
                mma16816(c0[0], c0[1], c0[2], c0[3],
                         qhf[kd][0], qhf[kd][1], qhf[kd][2], qhf[kd][3], kh0, kh2);
                mma16816(c1[0], c1[1], c1[2], c1[3],
                         qhf[kd][0], qhf[kd][1], qhf[kd][2], qhf[kd][3], kh1, kh3);
                mma16816(c0[0], c0[1], c0[2], c0[3],
                         qhf[kd][0], qhf[kd][1], qhf[kd][2], qhf[kd][3], kl0, kl2);
                mma16816(c1[0], c1[1], c1[2], c1[3],
                         qhf[kd][0], qhf[kd][1], qhf[kd][2], qhf[kd][3], kl1, kl3);
                mma16816(c0[0], c0[1], c0[2], c0[3],
                         qlf[kd][0], qlf[kd][1], qlf[kd][2], qlf[kd][3], kh0, kh2);
                mma16816(c1[0], c1[1], c1[2], c1[3],
                         qlf[kd][0], qlf[kd][1], qlf[kd][2], qlf[kd][3], kh1, kh3);
            }
        }

        if (kb * 64 + 63 > qb * 128 + wid * 16) {
            const int cb = kb * 64 + colg0;
            #pragma unroll
            for (int nt = 0; nt < 8; ++nt) {
                const int c0 = cb + nt * 8, c1 = c0 + 1;
                if (c0 > row0g) sacc[nt][0] = -1e30f;
                if (c1 > row0g) sacc[nt][1] = -1e30f;
                if (c0 > row0g + 8) sacc[nt][2] = -1e30f;
                if (c1 > row0g + 8) sacc[nt][3] = -1e30f;
            }
        }

        float mx0 = -1e30f, mx1 = -1e30f;
        #pragma unroll
        for (int nt = 0; nt < 8; ++nt) {
            mx0 = fmaxf(mx0, fmaxf(sacc[nt][0], sacc[nt][1]));
            mx1 = fmaxf(mx1, fmaxf(sacc[nt][2], sacc[nt][3]));
        }
        mx0 = fmaxf(mx0, __shfl_xor_sync(0xffffffffu, mx0, 1));
        mx0 = fmaxf(mx0, __shfl_xor_sync(0xffffffffu, mx0, 2));
        mx1 = fmaxf(mx1, __shfl_xor_sync(0xffffffffu, mx1, 1));
        mx1 = fmaxf(mx1, __shfl_xor_sync(0xffffffffu, mx1, 2));

        const float mn0 = fmaxf(mro0, mx0);
        const float mn1 = fmaxf(mro1, mx1);
        const float al0 = __expf(mro0 - mn0);
        const float al1 = __expf(mro1 - mn1);
        mro0 = mn0; mro1 = mn1;

        float rs0 = 0.f, rs1 = 0.f;
        #pragma unroll
        for (int nt = 0; nt < 8; ++nt) {
            float p0 = __expf(sacc[nt][0] - mn0);
            float p1 = __expf(sacc[nt][1] - mn0);
            float p2 = __expf(sacc[nt][2] - mn1);
            float p3 = __expf(sacc[nt][3] - mn1);
            sacc[nt][0] = p0; sacc[nt][1] = p1; sacc[nt][2] = p2; sacc[nt][3] = p3;
            rs0 += p0 + p1;
            rs1 += p2 + p3;
        }
        rs0 += __shfl_xor_sync(0xffffffffu, rs0, 1);
        rs0 += __shfl_xor_sync(0xffffffffu, rs0, 2);
        rs1 += __shfl_xor_sync(0xffffffffu, rs1, 1);
        rs1 += __shfl_xor_sync(0xffffffffu, rs1, 2);
        lro0 = lro0 * al0 + rs0;
        lro1 = lro1 * al1 + rs1;

        #pragma unroll
        for (int dt = 0; dt < 16; ++dt) {
            of[dt][0] *= al0; of[dt][1] *= al0;
            of[dt][2] *= al1; of[dt][3] *= al1;
        }

        uint32_t pah[4][4], pal[4][4];
        #pragma unroll
        for (int g = 0; g < 4; ++g) {
            const float* pe = sacc[2 * g];
            const float* po = sacc[2 * g + 1];
            pah[g][0] = packbf2(pe[0], pe[1]);
            pah[g][1] = packbf2(pe[2], pe[3]);
            pah[g][2] = packbf2(po[0], po[1]);
            pah[g][3] = packbf2(po[2], po[3]);
            __nv_bfloat162* bh;
            bh = (__nv_bfloat162*)&pah[g][0];
            pal[g][0] = packbf2(pe[0] - __bfloat162float(bh->x), pe[1] - __bfloat162float(bh->y));
            bh = (__nv_bfloat162*)&pah[g][1];
            pal[g][1] = packbf2(pe[2] - __bfloat162float(bh->x), pe[3] - __bfloat162float(bh->y));
            bh = (__nv_bfloat162*)&pah[g][2];
            pal[g][2] = packbf2(po[0] - __bfloat162float(bh->x), po[1] - __bfloat162float(bh->y));
            bh = (__nv_bfloat162*)&pah[g][3];
            pal[g][3] = packbf2(po[2] - __bfloat162float(bh->x), po[3] - __bfloat162float(bh->y));
        }

        #pragma unroll
        for (int g = 0; g < 4; ++g) {
            const uint32_t col = (uint32_t)(g * 32 + khalf) ^ xorv;
            #pragma unroll
            for (int dt = 0; dt < 8; ++dt) {
                const uint32_t rowb = (uint32_t)(dt * 16 + half_a * 8 + l7) * 128;
                uint32_t vh0, vh1, vh2, vh3, vl0, vl1, vl2, vl3;
                ldm4(vh0, vh1, vh2, vh3, base + 32768 + rowb + col);
                ldm4(vl0, vl1, vl2, vl3, base + 49152 + rowb + col);
                float* o0 = of[dt * 2];
                float* o1 = of[dt * 2 + 1];
                mma16816(o0[0], o0[1], o0[2], o0[3],
                         pah[g][0], pah[g][1], pah[g][2], pah[g][3], vh0, vh2);
                mma16816(o1[0], o1[1], o1[2], o1[3],
                         pah[g][0], pah[g][1], pah[g][2], pah[g][3], vh1, vh3);
                mma16816(o0[0], o0[1], o0[2], o0[3],
                         pah[g][0], pah[g][1], pah[g][2], pah[g][3], vl0, vl2);
                mma16816(o1[0], o1[1], o1[2], o1[3],
                         pah[g][0], pah[g][1], pah[g][2], pah[g][3], vl1, vl3);
                mma16816(o0[0], o0[1], o0[2], o0[3],
                         pal[g][0], pal[g][1], pal[g][2], pal[g][3], vh0, vh2);
                mma16816(o1[0], o1[1], o1[2], o1[3],
                         pal[g][0], pal[g][1], pal[g][2], pal[g][3], vh1, vh3);
            }
        }
    }

    // ---- epilogue: write bf16 hi/lo planes for the O-projection directly ----
    const float inv0 = 1.f / lro0;
    const float inv1 = 1.f / lro1;
    const size_t obase = qrowbase + (size_t)(wid * 16 + (lane >> 2)) * CC + colg0;
    #pragma unroll
    for (int dt = 0; dt < 16; ++dt) {
        float v00 = of[dt][0] * inv0, v01 = of[dt][1] * inv0;
        float v10 = of[dt][2] * inv1, v11 = of[dt][3] * inv1;
        __nv_bfloat16 h0, l0, h1, l1;
        split2(v00, h0, l0); split2(v01, h1, l1);
        *(__nv_bfloat162*)(g_yh + obase + dt * 8) = __nv_bfloat162(h0, h1);
        *(__nv_bfloat162*)(g_yl + obase + dt * 8) = __nv_bfloat162(l0, l1);
        split2(v10, h0, l0); split2(v11, h1, l1);
        *(__nv_bfloat162*)(g_yh + obase + 8 * CC + dt * 8) = __nv_bfloat162(h0, h1);
        *(__nv_bfloat162*)(g_yl + obase + 8 * CC + dt * 8) = __nv_bfloat162(l0, l1);
    }
}

// ---------------- launch ----------------
extern "C" void kernel_launch(void* const* d_in, const int* in_sizes, int n_in,
                              void* d_out, int out_size) {
    const float* x  = (const float*)d_in[0];
    const float* wq = (const float*)d_in[1];
    const float* wk = (const float*)d_in[2];
    const float* wv = (const float*)d_in[3];
    const float* wo = (const float*)d_in[4];
    float* out = (float*)d_out;

    float *q, *k;
    cudaGetSymbolAddress((void**)&q, g_q);
    cudaGetSymbolAddress((void**)&k, g_k);

    __nv_bfloat16 *xh, *xl, *yh, *yl;
    __nv_bfloat16 *wqh, *wql, *wkh, *wkl, *wvh, *wvl, *woh, *wol;
    cudaGetSymbolAddress((void**)&xh, g_xh);   cudaGetSymbolAddress((void**)&xl, g_xl);
    cudaGetSymbolAddress((void**)&yh, g_yh);   cudaGetSymbolAddress((void**)&yl, g_yl);
    cudaGetSymbolAddress((void**)&wqh, g_wqh); cudaGetSymbolAddress((void**)&wql, g_wql);
    cudaGetSymbolAddress((void**)&wkh, g_wkh); cudaGetSymbolAddress((void**)&wkl, g_wkl);
    cudaGetSymbolAddress((void**)&wvh, g_wvh); cudaGetSymbolAddress((void**)&wvl, g_wvl);
    cudaGetSymbolAddress((void**)&woh, g_woh); cudaGetSymbolAddress((void**)&wol, g_wol);

    rope_table_kernel<<<512, 256>>>();
    conv_split_kernel<<<(MM * CC) / 1024, 256>>>(x, xh, xl);
    conv_w4_kernel<<<dim3(CC / 32, CC / 32, 4), dim3(32, 8)>>>(wq, wk, wv, wo);

    cudaFuncSetAttribute(gemm_bf16x3, cudaFuncAttributeMaxDynamicSharedMemorySize, GEMM_SMEM);

    // fused QKV projection; z==2 (V) writes transposed bf16 planes directly
    gemm_bf16x3<<<dim3(CC / 128, MM / 64, 3), 256, GEMM_SMEM>>>(
        xh, xl, wqh, wql, wkh, wkl, wvh, wvl, q, k);

    rope_apply_split_kernel<<<(BB * TT * HH * 32) / 256, 256>>>();

    cudaFuncSetAttribute(attn_hmma, cudaFuncAttributeMaxDynamicSharedMemorySize, ATT_SMEM2);
    attn_hmma<<<dim3(TT / 128, HH, BB), 256, ATT_SMEM2>>>();

    // output projection (z==0 path, C0 = out)
    gemm_bf16x3<<<dim3(CC / 128, MM / 64, 1), 256, GEMM_SMEM>>>(
        yh, yl, woh, wol, woh, wol, woh, wol, out, out);
}